// round 6
// baseline (speedup 1.0000x reference)
#include <cuda_runtime.h>
#include <cuda_bf16.h>
#include <cstdint>

// ---------------------------------------------------------------------------
// GraphSAGE 2-layer, N=100000, E=1.6M, 128 -> 128 -> 64, fp32.
//
// Pipeline (all on default stream, graph-capturable, no allocations):
//   0. detect   : edge_index dtype probe (int64 vs int32)
//   1. zero     : agg0, agg1, cnt
//   2. gemm0    : y0 = x @ W_l0 ; z0 = x @ W_r0        (dual GEMM, shared A read)
//   3. scatter0 : agg0[dst] += y0[src] (vec RED), cnt[dst] += 1
//   4. fin0     : h = relu(agg0/max(cnt,1) + b_l0 + z0)
//   5. gemm1    : y1 = h @ W_l1 ; z1 = h @ W_r1
//   6. scatter1 : agg1[dst] += y1[src]
//   7. fin1     : out = agg1/max(cnt,1) + b_l1 + z1
// ---------------------------------------------------------------------------

#define MAXN 100000
#define MAXE 1600000
#define DIN  128
#define DHID 128
#define DOUT 64

__device__ __align__(16) float g_y0  [(size_t)MAXN * DHID];
__device__ __align__(16) float g_z0  [(size_t)MAXN * DHID];
__device__ __align__(16) float g_agg0[(size_t)MAXN * DHID];
__device__ __align__(16) float g_h   [(size_t)MAXN * DHID];
__device__ __align__(16) float g_y1  [(size_t)MAXN * DOUT];
__device__ __align__(16) float g_z1  [(size_t)MAXN * DOUT];
__device__ __align__(16) float g_agg1[(size_t)MAXN * DOUT];
__device__ __align__(16) float g_cnt [MAXN + 4];
__device__ int g_is64;

// ---------------------------------------------------------------------------
// 0. dtype probe: if buffer really holds int64 node ids, the first 64 values
// are all in [0, 2^31). If it holds int32 pairs read as int64, the high word
// is the *next* node id; probability all 64 high words are zero ~ 1e-320.
// ---------------------------------------------------------------------------
__global__ void detect_kernel(const long long* __restrict__ p) {
    if (threadIdx.x == 0 && blockIdx.x == 0) {
        int ok = 1;
        for (int i = 0; i < 64; i++) {
            long long v = p[i];
            if (v < 0 || v >= (1LL << 31)) { ok = 0; break; }
        }
        g_is64 = ok;
    }
}

// ---------------------------------------------------------------------------
// 1. zero scratch accumulators (float4 stores)
// ---------------------------------------------------------------------------
__global__ void zero_kernel(int N) {
    int i = blockIdx.x * blockDim.x + threadIdx.x;
    const float4 z = make_float4(0.f, 0.f, 0.f, 0.f);
    int n0 = N * (DHID / 4);          // agg0 float4s
    int n1 = N * (DOUT / 4);          // agg1 float4s
    int nc = (N + 3) / 4;             // cnt float4s
    if (i < n0)                 ((float4*)g_agg0)[i] = z;
    else if (i < n0 + n1)       ((float4*)g_agg1)[i - n0] = z;
    else if (i < n0 + n1 + nc)  ((float4*)g_cnt)[i - n0 - n1] = z;
}

// ---------------------------------------------------------------------------
// 2/5. dual GEMM: Yl = A @ Wl, Yr = A @ Wr.  A:[N,128], W:[128,CO], CO in {128,64}
// BM=64 rows/block, BK=16, 256 threads, thread tile 4 x (CO/16) per W.
// ---------------------------------------------------------------------------
template <int CO, int STAGE>
__global__ void __launch_bounds__(256)
gemm_dual_kernel(const float* __restrict__ Aext,
                 const float* __restrict__ Wl,
                 const float* __restrict__ Wr,
                 int N)
{
    constexpr int BM = 64, BK = 16, K = 128;
    constexpr int TM = 4, TN = CO / 16;

    const float* __restrict__ A  = (STAGE == 0) ? Aext : g_h;
    float* __restrict__ Yl       = (STAGE == 0) ? g_y0 : g_y1;
    float* __restrict__ Yr       = (STAGE == 0) ? g_z0 : g_z1;

    __shared__ __align__(16) float As[BK][BM];
    __shared__ __align__(16) float Bl[BK][CO];
    __shared__ __align__(16) float Br[BK][CO];

    const int tid = threadIdx.x;
    const int tx  = tid & 15;          // col group
    const int ty  = tid >> 4;          // row group
    const int row0 = blockIdx.x * BM;

    float accl[TM][TN];
    float accr[TM][TN];
#pragma unroll
    for (int i = 0; i < TM; i++)
#pragma unroll
        for (int j = 0; j < TN; j++) { accl[i][j] = 0.f; accr[i][j] = 0.f; }

    for (int k0 = 0; k0 < K; k0 += BK) {
        // --- stage A chunk (transposed) : 64 rows x 16 k, 1 float4/thread ---
        {
            int r  = tid >> 2;             // 0..63
            int kk = (tid & 3) * 4;        // 0,4,8,12
            int grow = row0 + r;
            float4 v = (grow < N)
                ? *(const float4*)(A + (size_t)grow * K + k0 + kk)
                : make_float4(0.f, 0.f, 0.f, 0.f);
            As[kk + 0][r] = v.x; As[kk + 1][r] = v.y;
            As[kk + 2][r] = v.z; As[kk + 3][r] = v.w;
        }
        // --- stage W chunks: BK*CO floats each ---
        for (int i = tid * 4; i < BK * CO; i += 256 * 4) {
            int kk = i / CO, c = i % CO;
            *(float4*)&Bl[kk][c] = *(const float4*)(Wl + (size_t)(k0 + kk) * CO + c);
            *(float4*)&Br[kk][c] = *(const float4*)(Wr + (size_t)(k0 + kk) * CO + c);
        }
        __syncthreads();

#pragma unroll
        for (int kk = 0; kk < BK; kk++) {
            const float4 av = *(const float4*)&As[kk][ty * 4];
            float a[4] = {av.x, av.y, av.z, av.w};
            float bl[TN], br[TN];
#pragma unroll
            for (int j = 0; j < TN; j += 4) {
                float4 t = *(const float4*)&Bl[kk][tx * TN + j];
                bl[j] = t.x; bl[j+1] = t.y; bl[j+2] = t.z; bl[j+3] = t.w;
                float4 u = *(const float4*)&Br[kk][tx * TN + j];
                br[j] = u.x; br[j+1] = u.y; br[j+2] = u.z; br[j+3] = u.w;
            }
#pragma unroll
            for (int i = 0; i < TM; i++)
#pragma unroll
                for (int j = 0; j < TN; j++) {
                    accl[i][j] = fmaf(a[i], bl[j], accl[i][j]);
                    accr[i][j] = fmaf(a[i], br[j], accr[i][j]);
                }
        }
        __syncthreads();
    }

#pragma unroll
    for (int i = 0; i < TM; i++) {
        int grow = row0 + ty * TM + i;
        if (grow < N) {
#pragma unroll
            for (int j = 0; j < TN; j += 4) {
                *(float4*)(Yl + (size_t)grow * CO + tx * TN + j) =
                    make_float4(accl[i][j], accl[i][j+1], accl[i][j+2], accl[i][j+3]);
                *(float4*)(Yr + (size_t)grow * CO + tx * TN + j) =
                    make_float4(accr[i][j], accr[i][j+1], accr[i][j+2], accr[i][j+3]);
            }
        }
    }
}

// ---------------------------------------------------------------------------
// vector reduction helper
// ---------------------------------------------------------------------------
__device__ __forceinline__ void red_add_v4(float* ptr, float4 v) {
    asm volatile("red.global.add.v4.f32 [%0], {%1, %2, %3, %4};"
                 :: "l"(ptr), "f"(v.x), "f"(v.y), "f"(v.z), "f"(v.w)
                 : "memory");
}

// ---------------------------------------------------------------------------
// 3. scatter layer 0: warp per edge, 128 floats = 1 float4/lane
// ---------------------------------------------------------------------------
__global__ void scatter0_kernel(const void* __restrict__ ei, int E) {
    unsigned tid  = blockIdx.x * blockDim.x + threadIdx.x;
    unsigned e    = tid >> 5;
    unsigned lane = tid & 31;
    if (e >= (unsigned)E) return;

    long long s, d;
    if (g_is64) {
        const long long* p = (const long long*)ei;
        s = p[e]; d = p[(size_t)E + e];
    } else {
        const int* p = (const int*)ei;
        s = p[e]; d = p[(size_t)E + e];
    }
    float4 v = *(const float4*)(g_y0 + (size_t)s * DHID + lane * 4);
    red_add_v4(g_agg0 + (size_t)d * DHID + lane * 4, v);
    if (lane == 0) atomicAdd(g_cnt + d, 1.0f);
}

// ---------------------------------------------------------------------------
// 6. scatter layer 1: half-warp per edge, 64 floats = 1 float4/lane16
// ---------------------------------------------------------------------------
__global__ void scatter1_kernel(const void* __restrict__ ei, int E) {
    unsigned tid = blockIdx.x * blockDim.x + threadIdx.x;
    unsigned e   = tid >> 4;
    unsigned l   = tid & 15;
    if (e >= (unsigned)E) return;

    long long s, d;
    if (g_is64) {
        const long long* p = (const long long*)ei;
        s = p[e]; d = p[(size_t)E + e];
    } else {
        const int* p = (const int*)ei;
        s = p[e]; d = p[(size_t)E + e];
    }
    float4 v = *(const float4*)(g_y1 + (size_t)s * DOUT + l * 4);
    red_add_v4(g_agg1 + (size_t)d * DOUT + l * 4, v);
}

// ---------------------------------------------------------------------------
// 4. finalize layer 0: h = relu(agg0 / max(cnt,1) + b_l0 + z0)
// ---------------------------------------------------------------------------
__global__ void fin0_kernel(const float* __restrict__ b, int N) {
    int i = blockIdx.x * blockDim.x + threadIdx.x;   // one float4
    if (i >= N * (DHID / 4)) return;
    int node = i >> 5;                                // 32 float4 per node
    int c4   = i & 31;
    float inv = 1.0f / fmaxf(g_cnt[node], 1.0f);
    float4 a  = ((const float4*)g_agg0)[i];
    float4 z  = ((const float4*)g_z0)[i];
    float4 bb = ((const float4*)b)[c4];
    float4 r;
    r.x = fmaxf(fmaf(a.x, inv, bb.x + z.x), 0.f);
    r.y = fmaxf(fmaf(a.y, inv, bb.y + z.y), 0.f);
    r.z = fmaxf(fmaf(a.z, inv, bb.z + z.z), 0.f);
    r.w = fmaxf(fmaf(a.w, inv, bb.w + z.w), 0.f);
    ((float4*)g_h)[i] = r;
}

// ---------------------------------------------------------------------------
// 7. finalize layer 1: out = agg1 / max(cnt,1) + b_l1 + z1
// ---------------------------------------------------------------------------
__global__ void fin1_kernel(const float* __restrict__ b, float* __restrict__ out, int N) {
    int i = blockIdx.x * blockDim.x + threadIdx.x;
    if (i >= N * (DOUT / 4)) return;
    int node = i >> 4;                                // 16 float4 per node
    int c4   = i & 15;
    float inv = 1.0f / fmaxf(g_cnt[node], 1.0f);
    float4 a  = ((const float4*)g_agg1)[i];
    float4 z  = ((const float4*)g_z1)[i];
    float4 bb = ((const float4*)b)[c4];
    float4 r;
    r.x = fmaf(a.x, inv, bb.x + z.x);
    r.y = fmaf(a.y, inv, bb.y + z.y);
    r.z = fmaf(a.z, inv, bb.z + z.z);
    r.w = fmaf(a.w, inv, bb.w + z.w);
    ((float4*)out)[i] = r;
}

// ---------------------------------------------------------------------------
extern "C" void kernel_launch(void* const* d_in, const int* in_sizes, int n_in,
                              void* d_out, int out_size) {
    const float* x    = (const float*)d_in[0];
    const void*  ei   = d_in[1];
    const float* W_l0 = (const float*)d_in[2];
    const float* b_l0 = (const float*)d_in[3];
    const float* W_r0 = (const float*)d_in[4];
    const float* W_l1 = (const float*)d_in[5];
    const float* b_l1 = (const float*)d_in[6];
    const float* W_r1 = (const float*)d_in[7];

    const int N = in_sizes[0] / DIN;
    const int E = in_sizes[1] / 2;

    // 0. edge dtype probe
    detect_kernel<<<1, 32>>>((const long long*)ei);

    // 1. zero accumulators
    {
        int total = N * (DHID / 4) + N * (DOUT / 4) + (N + 3) / 4;
        zero_kernel<<<(total + 255) / 256, 256>>>(N);
    }

    // 2. layer-0 dual GEMM
    gemm_dual_kernel<DHID, 0><<<(N + 63) / 64, 256>>>(x, W_l0, W_r0, N);

    // 3. layer-0 scatter (warp/edge)
    {
        long long threads = (long long)E * 32;
        scatter0_kernel<<<(unsigned)((threads + 255) / 256), 256>>>(ei, E);
    }

    // 4. finalize h
    fin0_kernel<<<(N * (DHID / 4) + 255) / 256, 256>>>(b_l0, N);

    // 5. layer-1 dual GEMM
    gemm_dual_kernel<DOUT, 1><<<(N + 63) / 64, 256>>>(nullptr, W_l1, W_r1, N);

    // 6. layer-1 scatter (half-warp/edge)
    {
        long long threads = (long long)E * 16;
        scatter1_kernel<<<(unsigned)((threads + 255) / 256), 256>>>(ei, E);
    }

    // 7. finalize output
    fin1_kernel<<<(N * (DOUT / 4) + 255) / 256, 256>>>(b_l1, (float*)d_out, N);
}

// round 7
// speedup vs baseline: 1.0738x; 1.0738x over previous
#include <cuda_runtime.h>
#include <cuda_bf16.h>
#include <cstdint>

// ---------------------------------------------------------------------------
// GraphSAGE 2-layer, N=100000, E=1.6M, 128 -> 128 -> 64, fp32.
//
// R7: pull-mode aggregation over on-device CSR (counting sort by dst).
// Removes all RED/atomic lane-ops from the hot edge loops (the R6 binder:
// REDG issue cost ~27 cyc/warp-instr/SM on 51.2M lane-reductions).
//
// Pipeline (single stream, graph-capturable, allocation-free):
//   0. detect   : edge dtype probe (int64 vs int32)
//   1. zc       : zero per-node counters
//   2. hist     : counts[dst]++                  (1 lane-atomic/edge)
//   3. scan     : exclusive prefix -> rowptr, wroff
//   4. permute  : srcs[atomicAdd(wroff[dst])] = src   (counting sort)
//   5. gemm0    : y0 = x @ W_l0 ; z0 = x @ W_r0
//   6. agg0     : warp/node: h = relu(mean_gather(y0) + b_l0 + z0)   [fused fin0]
//   7. gemm1    : y1 = h @ W_l1 ; z1 = h @ W_r1
//   8. agg1     : half-warp/node: out = mean_gather(y1) + b_l1 + z1  [fused fin1]
// ---------------------------------------------------------------------------

#define MAXN 100000
#define MAXE 1600000
#define DIN  128
#define DHID 128
#define DOUT 64

__device__ __align__(16) float g_y0[(size_t)MAXN * DHID];
__device__ __align__(16) float g_z0[(size_t)MAXN * DHID];
__device__ __align__(16) float g_h [(size_t)MAXN * DHID];
__device__ __align__(16) float g_y1[(size_t)MAXN * DOUT];
__device__ __align__(16) float g_z1[(size_t)MAXN * DOUT];
__device__ int g_rowptr[MAXN + 1];
__device__ int g_wroff [MAXN + 1];   // counts, then write cursors
__device__ int g_srcs  [MAXE];       // src ids sorted by dst
__device__ int g_is64;

// ---------------------------------------------------------------------------
// 0. dtype probe: true int64 ids are all in [0, 2^31); int32 data read as
// int64 would make high words = next id (nonzero w.p. ~1).
// ---------------------------------------------------------------------------
__global__ void detect_kernel(const long long* __restrict__ p) {
    if (threadIdx.x == 0 && blockIdx.x == 0) {
        int ok = 1;
        for (int i = 0; i < 64; i++) {
            long long v = p[i];
            if (v < 0 || v >= (1LL << 31)) { ok = 0; break; }
        }
        g_is64 = ok;
    }
}

// ---------------------------------------------------------------------------
// 1. zero counters
// ---------------------------------------------------------------------------
__global__ void zc_kernel(int N) {
    int i = blockIdx.x * blockDim.x + threadIdx.x;
    if (i <= N) g_wroff[i] = 0;
}

// ---------------------------------------------------------------------------
// helpers to read edge ids under either dtype
// ---------------------------------------------------------------------------
__device__ __forceinline__ int edge_id(const void* ei, size_t idx) {
    return g_is64 ? (int)((const long long*)ei)[idx]
                  : ((const int*)ei)[idx];
}

// ---------------------------------------------------------------------------
// 2. histogram of dst
// ---------------------------------------------------------------------------
__global__ void hist_kernel(const void* __restrict__ ei, int E) {
    int e = blockIdx.x * blockDim.x + threadIdx.x;
    if (e >= E) return;
    int d = edge_id(ei, (size_t)E + e);
    atomicAdd(&g_wroff[d], 1);
}

// ---------------------------------------------------------------------------
// 3. single-block exclusive scan (1024 threads, ~98 elems/thread serial)
// ---------------------------------------------------------------------------
__global__ void __launch_bounds__(1024)
scan_kernel(int N, int E) {
    __shared__ int sums[1024];
    const int t  = threadIdx.x;
    const int ch = (N + 1023) / 1024;
    const int lo = t * ch;
    const int hi = min(lo + ch, N);

    int s = 0;
    for (int i = lo; i < hi; i++) s += g_wroff[i];
    sums[t] = s;
    __syncthreads();
    // Hillis-Steele inclusive scan
    for (int off = 1; off < 1024; off <<= 1) {
        int v = (t >= off) ? sums[t - off] : 0;
        __syncthreads();
        sums[t] += v;
        __syncthreads();
    }
    int run = (t == 0) ? 0 : sums[t - 1];
    for (int i = lo; i < hi; i++) {
        int c = g_wroff[i];
        g_rowptr[i] = run;
        g_wroff[i]  = run;
        run += c;
    }
    if (t == 0) g_rowptr[N] = E;
}

// ---------------------------------------------------------------------------
// 4. counting-sort permute: srcs grouped by dst
// ---------------------------------------------------------------------------
__global__ void permute_kernel(const void* __restrict__ ei, int E) {
    int e = blockIdx.x * blockDim.x + threadIdx.x;
    if (e >= E) return;
    int s = edge_id(ei, (size_t)e);
    int d = edge_id(ei, (size_t)E + e);
    int pos = atomicAdd(&g_wroff[d], 1);
    g_srcs[pos] = s;
}

// ---------------------------------------------------------------------------
// 5/7. dual GEMM: Yl = A @ Wl, Yr = A @ Wr.  A:[N,128], W:[128,CO]
// ---------------------------------------------------------------------------
template <int CO, int STAGE>
__global__ void __launch_bounds__(256)
gemm_dual_kernel(const float* __restrict__ Aext,
                 const float* __restrict__ Wl,
                 const float* __restrict__ Wr,
                 int N)
{
    constexpr int BM = 64, BK = 16, K = 128;
    constexpr int TM = 4, TN = CO / 16;

    const float* __restrict__ A = (STAGE == 0) ? Aext : g_h;
    float* __restrict__ Yl      = (STAGE == 0) ? g_y0 : g_y1;
    float* __restrict__ Yr      = (STAGE == 0) ? g_z0 : g_z1;

    __shared__ __align__(16) float As[BK][BM];
    __shared__ __align__(16) float Bl[BK][CO];
    __shared__ __align__(16) float Br[BK][CO];

    const int tid = threadIdx.x;
    const int tx  = tid & 15;
    const int ty  = tid >> 4;
    const int row0 = blockIdx.x * BM;

    float accl[TM][TN], accr[TM][TN];
#pragma unroll
    for (int i = 0; i < TM; i++)
#pragma unroll
        for (int j = 0; j < TN; j++) { accl[i][j] = 0.f; accr[i][j] = 0.f; }

    for (int k0 = 0; k0 < K; k0 += BK) {
        {
            int r  = tid >> 2;
            int kk = (tid & 3) * 4;
            int grow = row0 + r;
            float4 v = (grow < N)
                ? *(const float4*)(A + (size_t)grow * K + k0 + kk)
                : make_float4(0.f, 0.f, 0.f, 0.f);
            As[kk + 0][r] = v.x; As[kk + 1][r] = v.y;
            As[kk + 2][r] = v.z; As[kk + 3][r] = v.w;
        }
        for (int i = tid * 4; i < BK * CO; i += 256 * 4) {
            int kk = i / CO, c = i % CO;
            *(float4*)&Bl[kk][c] = *(const float4*)(Wl + (size_t)(k0 + kk) * CO + c);
            *(float4*)&Br[kk][c] = *(const float4*)(Wr + (size_t)(k0 + kk) * CO + c);
        }
        __syncthreads();

#pragma unroll
        for (int kk = 0; kk < BK; kk++) {
            const float4 av = *(const float4*)&As[kk][ty * 4];
            float a[4] = {av.x, av.y, av.z, av.w};
            float bl[TN], br[TN];
#pragma unroll
            for (int j = 0; j < TN; j += 4) {
                float4 t = *(const float4*)&Bl[kk][tx * TN + j];
                bl[j] = t.x; bl[j+1] = t.y; bl[j+2] = t.z; bl[j+3] = t.w;
                float4 u = *(const float4*)&Br[kk][tx * TN + j];
                br[j] = u.x; br[j+1] = u.y; br[j+2] = u.z; br[j+3] = u.w;
            }
#pragma unroll
            for (int i = 0; i < TM; i++)
#pragma unroll
                for (int j = 0; j < TN; j++) {
                    accl[i][j] = fmaf(a[i], bl[j], accl[i][j]);
                    accr[i][j] = fmaf(a[i], br[j], accr[i][j]);
                }
        }
        __syncthreads();
    }

#pragma unroll
    for (int i = 0; i < TM; i++) {
        int grow = row0 + ty * TM + i;
        if (grow < N) {
#pragma unroll
            for (int j = 0; j < TN; j += 4) {
                *(float4*)(Yl + (size_t)grow * CO + tx * TN + j) =
                    make_float4(accl[i][j], accl[i][j+1], accl[i][j+2], accl[i][j+3]);
                *(float4*)(Yr + (size_t)grow * CO + tx * TN + j) =
                    make_float4(accr[i][j], accr[i][j+1], accr[i][j+2], accr[i][j+3]);
            }
        }
    }
}

// ---------------------------------------------------------------------------
// 6. layer-0 pull aggregation + fused finalize:
//    warp/node, lane l owns cols [4l, 4l+4). No atomics.
//    h = relu(sum(y0[src]) / max(deg,1) + b_l0 + z0)
// ---------------------------------------------------------------------------
__global__ void agg0_kernel(const float* __restrict__ b, int N) {
    int warp = (blockIdx.x * blockDim.x + threadIdx.x) >> 5;
    int lane = threadIdx.x & 31;
    if (warp >= N) return;

    const int beg = g_rowptr[warp];
    const int end = g_rowptr[warp + 1];

    float4 acc = make_float4(0.f, 0.f, 0.f, 0.f);
    int j = beg;
    int s = (j < end) ? g_srcs[j] : 0;
    for (; j < end; j++) {
        int snext = (j + 1 < end) ? g_srcs[j + 1] : 0;   // prefetch id
        float4 v = *(const float4*)(g_y0 + (size_t)s * DHID + lane * 4);
        acc.x += v.x; acc.y += v.y; acc.z += v.z; acc.w += v.w;
        s = snext;
    }

    float inv = 1.0f / fmaxf((float)(end - beg), 1.0f);
    float4 z  = *(const float4*)(g_z0 + (size_t)warp * DHID + lane * 4);
    float4 bb = ((const float4*)b)[lane];
    float4 r;
    r.x = fmaxf(fmaf(acc.x, inv, bb.x + z.x), 0.f);
    r.y = fmaxf(fmaf(acc.y, inv, bb.y + z.y), 0.f);
    r.z = fmaxf(fmaf(acc.z, inv, bb.z + z.z), 0.f);
    r.w = fmaxf(fmaf(acc.w, inv, bb.w + z.w), 0.f);
    *(float4*)(g_h + (size_t)warp * DHID + lane * 4) = r;
}

// ---------------------------------------------------------------------------
// 8. layer-1 pull aggregation + fused finalize: half-warp/node -> d_out
// ---------------------------------------------------------------------------
__global__ void agg1_kernel(const float* __restrict__ b,
                            float* __restrict__ out, int N) {
    int tid  = blockIdx.x * blockDim.x + threadIdx.x;
    int node = tid >> 4;
    int l    = tid & 15;
    if (node >= N) return;

    const int beg = g_rowptr[node];
    const int end = g_rowptr[node + 1];

    float4 acc = make_float4(0.f, 0.f, 0.f, 0.f);
    int j = beg;
    int s = (j < end) ? g_srcs[j] : 0;
    for (; j < end; j++) {
        int snext = (j + 1 < end) ? g_srcs[j + 1] : 0;
        float4 v = *(const float4*)(g_y1 + (size_t)s * DOUT + l * 4);
        acc.x += v.x; acc.y += v.y; acc.z += v.z; acc.w += v.w;
        s = snext;
    }

    float inv = 1.0f / fmaxf((float)(end - beg), 1.0f);
    float4 z  = *(const float4*)(g_z1 + (size_t)node * DOUT + l * 4);
    float4 bb = ((const float4*)b)[l];
    float4 r;
    r.x = fmaf(acc.x, inv, bb.x + z.x);
    r.y = fmaf(acc.y, inv, bb.y + z.y);
    r.z = fmaf(acc.z, inv, bb.z + z.z);
    r.w = fmaf(acc.w, inv, bb.w + z.w);
    *(float4*)(out + (size_t)node * DOUT + l * 4) = r;
}

// ---------------------------------------------------------------------------
extern "C" void kernel_launch(void* const* d_in, const int* in_sizes, int n_in,
                              void* d_out, int out_size) {
    const float* x    = (const float*)d_in[0];
    const void*  ei   = d_in[1];
    const float* W_l0 = (const float*)d_in[2];
    const float* b_l0 = (const float*)d_in[3];
    const float* W_r0 = (const float*)d_in[4];
    const float* W_l1 = (const float*)d_in[5];
    const float* b_l1 = (const float*)d_in[6];
    const float* W_r1 = (const float*)d_in[7];

    const int N = in_sizes[0] / DIN;
    const int E = in_sizes[1] / 2;

    // 0. edge dtype probe
    detect_kernel<<<1, 32>>>((const long long*)ei);

    // 1-4. CSR build (counting sort by dst)
    zc_kernel<<<(N + 256) / 256, 256>>>(N);
    hist_kernel<<<(E + 255) / 256, 256>>>(ei, E);
    scan_kernel<<<1, 1024>>>(N, E);
    permute_kernel<<<(E + 255) / 256, 256>>>(ei, E);

    // 5. layer-0 dual GEMM
    gemm_dual_kernel<DHID, 0><<<(N + 63) / 64, 256>>>(x, W_l0, W_r0, N);

    // 6. layer-0 aggregation + finalize (warp/node)
    {
        long long threads = (long long)N * 32;
        agg0_kernel<<<(unsigned)((threads + 255) / 256), 256>>>(b_l0, N);
    }

    // 7. layer-1 dual GEMM
    gemm_dual_kernel<DOUT, 1><<<(N + 63) / 64, 256>>>(nullptr, W_l1, W_r1, N);

    // 8. layer-1 aggregation + finalize (half-warp/node)
    {
        long long threads = (long long)N * 16;
        agg1_kernel<<<(unsigned)((threads + 255) / 256), 256>>>(b_l1, (float*)d_out, N);
    }
}

// round 8
// speedup vs baseline: 1.3086x; 1.2186x over previous
#include <cuda_runtime.h>
#include <cuda_bf16.h>
#include <cstdint>

// ---------------------------------------------------------------------------
// GraphSAGE 2-layer, N=100000, E=1.6M, 128 -> 128 -> 64, fp32.
//
// R8: multi-block CSR prefix scan (R7's single-block scan_kernel was 144us
// on one SM; replaced by reduce -> block-sum scan -> local scan, ~10us).
//
// Pipeline (single stream, graph-capturable, allocation-free):
//   0. detect   : edge dtype probe (int64 vs int32)
//   1. zc       : zero per-node counters
//   2. hist     : counts[dst]++
//   3a. breduce : per-1024-chunk partial sums
//   3b. bscan   : scan partials (1 tiny block)
//   3c. lscan   : in-block exclusive scan + offset -> rowptr, wroff
//   4. permute  : srcs[atomicAdd(wroff[dst])] = src   (counting sort)
//   5. gemm0    : y0 = x @ W_l0 ; z0 = x @ W_r0
//   6. agg0     : warp/node: h = relu(mean_gather(y0) + b_l0 + z0)
//   7. gemm1    : y1 = h @ W_l1 ; z1 = h @ W_r1
//   8. agg1     : half-warp/node: out = mean_gather(y1) + b_l1 + z1
// ---------------------------------------------------------------------------

#define MAXN 100000
#define MAXE 1600000
#define DIN  128
#define DHID 128
#define DOUT 64

#define SCAN_CHUNK 1024           // counts per scan block (256 thr x 4)
#define MAXB ((MAXN + SCAN_CHUNK - 1) / SCAN_CHUNK + 1)

__device__ __align__(16) float g_y0[(size_t)MAXN * DHID];
__device__ __align__(16) float g_z0[(size_t)MAXN * DHID];
__device__ __align__(16) float g_h [(size_t)MAXN * DHID];
__device__ __align__(16) float g_y1[(size_t)MAXN * DOUT];
__device__ __align__(16) float g_z1[(size_t)MAXN * DOUT];
__device__ int g_rowptr[MAXN + 1];
__device__ int g_wroff [MAXN + 1];   // counts, then write cursors
__device__ int g_srcs  [MAXE];       // src ids sorted by dst
__device__ int g_bsum  [MAXB];       // per-chunk partial sums -> exclusive prefix
__device__ int g_is64;

// ---------------------------------------------------------------------------
// 0. dtype probe
// ---------------------------------------------------------------------------
__global__ void detect_kernel(const long long* __restrict__ p) {
    if (threadIdx.x == 0 && blockIdx.x == 0) {
        int ok = 1;
        for (int i = 0; i < 64; i++) {
            long long v = p[i];
            if (v < 0 || v >= (1LL << 31)) { ok = 0; break; }
        }
        g_is64 = ok;
    }
}

// ---------------------------------------------------------------------------
// 1. zero counters
// ---------------------------------------------------------------------------
__global__ void zc_kernel(int N) {
    int i = blockIdx.x * blockDim.x + threadIdx.x;
    if (i <= N) g_wroff[i] = 0;
}

__device__ __forceinline__ int edge_id(const void* ei, size_t idx) {
    return g_is64 ? (int)((const long long*)ei)[idx]
                  : ((const int*)ei)[idx];
}

// ---------------------------------------------------------------------------
// 2. histogram of dst
// ---------------------------------------------------------------------------
__global__ void hist_kernel(const void* __restrict__ ei, int E) {
    int e = blockIdx.x * blockDim.x + threadIdx.x;
    if (e >= E) return;
    int d = edge_id(ei, (size_t)E + e);
    atomicAdd(&g_wroff[d], 1);
}

// ---------------------------------------------------------------------------
// 3a. per-chunk reduce: g_bsum[b] = sum of counts in [b*1024, b*1024+1024)
// ---------------------------------------------------------------------------
__global__ void __launch_bounds__(256)
breduce_kernel(int N) {
    __shared__ int sh[8];
    int t = threadIdx.x;
    int base = blockIdx.x * SCAN_CHUNK + t * 4;
    int s = 0;
#pragma unroll
    for (int i = 0; i < 4; i++) {
        int idx = base + i;
        if (idx < N) s += g_wroff[idx];
    }
#pragma unroll
    for (int off = 16; off > 0; off >>= 1)
        s += __shfl_down_sync(0xffffffffu, s, off);
    if ((t & 31) == 0) sh[t >> 5] = s;
    __syncthreads();
    if (t == 0) {
        int tot = 0;
#pragma unroll
        for (int i = 0; i < 8; i++) tot += sh[i];
        g_bsum[blockIdx.x] = tot;
    }
}

// ---------------------------------------------------------------------------
// 3b. scan the chunk partials (nb <= 128 for N=100K); also set rowptr[N]
// ---------------------------------------------------------------------------
__global__ void __launch_bounds__(256)
bscan_kernel(int nb, int N, int E) {
    __shared__ int sh[256];
    int t = threadIdx.x;
    int v = (t < nb) ? g_bsum[t] : 0;
    sh[t] = v;
    __syncthreads();
    for (int off = 1; off < 256; off <<= 1) {
        int u = (t >= off) ? sh[t - off] : 0;
        __syncthreads();
        sh[t] += u;
        __syncthreads();
    }
    if (t < nb) g_bsum[t] = sh[t] - v;   // exclusive prefix
    if (t == 0) g_rowptr[N] = E;
}

// ---------------------------------------------------------------------------
// 3c. in-chunk exclusive scan + global offset -> rowptr & wroff
// ---------------------------------------------------------------------------
__global__ void __launch_bounds__(256)
lscan_kernel(int N) {
    __shared__ int wsum[8];
    int t    = threadIdx.x;
    int lane = t & 31;
    int wid  = t >> 5;
    int base = blockIdx.x * SCAN_CHUNK + t * 4;

    int c[4];
#pragma unroll
    for (int i = 0; i < 4; i++) {
        int idx = base + i;
        c[i] = (idx < N) ? g_wroff[idx] : 0;
    }
    int tsum = c[0] + c[1] + c[2] + c[3];

    // warp inclusive scan of per-thread sums
    int incl = tsum;
#pragma unroll
    for (int off = 1; off < 32; off <<= 1) {
        int u = __shfl_up_sync(0xffffffffu, incl, off);
        if (lane >= off) incl += u;
    }
    if (lane == 31) wsum[wid] = incl;
    __syncthreads();
    if (wid == 0) {
        int w = (lane < 8) ? wsum[lane] : 0;
#pragma unroll
        for (int off = 1; off < 8; off <<= 1) {
            int u = __shfl_up_sync(0xffffffffu, w, off);
            if (lane >= off) w += u;
        }
        if (lane < 8) wsum[lane] = w;   // inclusive over warps
    }
    __syncthreads();

    int run = incl - tsum                       // exclusive within warp
            + ((wid > 0) ? wsum[wid - 1] : 0)   // warps before
            + g_bsum[blockIdx.x];               // chunks before
#pragma unroll
    for (int i = 0; i < 4; i++) {
        int idx = base + i;
        if (idx < N) { g_rowptr[idx] = run; g_wroff[idx] = run; run += c[i]; }
    }
}

// ---------------------------------------------------------------------------
// 4. counting-sort permute: srcs grouped by dst
// ---------------------------------------------------------------------------
__global__ void permute_kernel(const void* __restrict__ ei, int E) {
    int e = blockIdx.x * blockDim.x + threadIdx.x;
    if (e >= E) return;
    int s = edge_id(ei, (size_t)e);
    int d = edge_id(ei, (size_t)E + e);
    int pos = atomicAdd(&g_wroff[d], 1);
    g_srcs[pos] = s;
}

// ---------------------------------------------------------------------------
// 5/7. dual GEMM: Yl = A @ Wl, Yr = A @ Wr.  A:[N,128], W:[128,CO]
// ---------------------------------------------------------------------------
template <int CO, int STAGE>
__global__ void __launch_bounds__(256)
gemm_dual_kernel(const float* __restrict__ Aext,
                 const float* __restrict__ Wl,
                 const float* __restrict__ Wr,
                 int N)
{
    constexpr int BM = 64, BK = 16, K = 128;
    constexpr int TM = 4, TN = CO / 16;

    const float* __restrict__ A = (STAGE == 0) ? Aext : g_h;
    float* __restrict__ Yl      = (STAGE == 0) ? g_y0 : g_y1;
    float* __restrict__ Yr      = (STAGE == 0) ? g_z0 : g_z1;

    __shared__ __align__(16) float As[BK][BM];
    __shared__ __align__(16) float Bl[BK][CO];
    __shared__ __align__(16) float Br[BK][CO];

    const int tid = threadIdx.x;
    const int tx  = tid & 15;
    const int ty  = tid >> 4;
    const int row0 = blockIdx.x * BM;

    float accl[TM][TN], accr[TM][TN];
#pragma unroll
    for (int i = 0; i < TM; i++)
#pragma unroll
        for (int j = 0; j < TN; j++) { accl[i][j] = 0.f; accr[i][j] = 0.f; }

    for (int k0 = 0; k0 < K; k0 += BK) {
        {
            int r  = tid >> 2;
            int kk = (tid & 3) * 4;
            int grow = row0 + r;
            float4 v = (grow < N)
                ? *(const float4*)(A + (size_t)grow * K + k0 + kk)
                : make_float4(0.f, 0.f, 0.f, 0.f);
            As[kk + 0][r] = v.x; As[kk + 1][r] = v.y;
            As[kk + 2][r] = v.z; As[kk + 3][r] = v.w;
        }
        for (int i = tid * 4; i < BK * CO; i += 256 * 4) {
            int kk = i / CO, c = i % CO;
            *(float4*)&Bl[kk][c] = *(const float4*)(Wl + (size_t)(k0 + kk) * CO + c);
            *(float4*)&Br[kk][c] = *(const float4*)(Wr + (size_t)(k0 + kk) * CO + c);
        }
        __syncthreads();

#pragma unroll
        for (int kk = 0; kk < BK; kk++) {
            const float4 av = *(const float4*)&As[kk][ty * 4];
            float a[4] = {av.x, av.y, av.z, av.w};
            float bl[TN], br[TN];
#pragma unroll
            for (int j = 0; j < TN; j += 4) {
                float4 t = *(const float4*)&Bl[kk][tx * TN + j];
                bl[j] = t.x; bl[j+1] = t.y; bl[j+2] = t.z; bl[j+3] = t.w;
                float4 u = *(const float4*)&Br[kk][tx * TN + j];
                br[j] = u.x; br[j+1] = u.y; br[j+2] = u.z; br[j+3] = u.w;
            }
#pragma unroll
            for (int i = 0; i < TM; i++)
#pragma unroll
                for (int j = 0; j < TN; j++) {
                    accl[i][j] = fmaf(a[i], bl[j], accl[i][j]);
                    accr[i][j] = fmaf(a[i], br[j], accr[i][j]);
                }
        }
        __syncthreads();
    }

#pragma unroll
    for (int i = 0; i < TM; i++) {
        int grow = row0 + ty * TM + i;
        if (grow < N) {
#pragma unroll
            for (int j = 0; j < TN; j += 4) {
                *(float4*)(Yl + (size_t)grow * CO + tx * TN + j) =
                    make_float4(accl[i][j], accl[i][j+1], accl[i][j+2], accl[i][j+3]);
                *(float4*)(Yr + (size_t)grow * CO + tx * TN + j) =
                    make_float4(accr[i][j], accr[i][j+1], accr[i][j+2], accr[i][j+3]);
            }
        }
    }
}

// ---------------------------------------------------------------------------
// 6. layer-0 pull aggregation + fused finalize (warp/node, no atomics)
// ---------------------------------------------------------------------------
__global__ void agg0_kernel(const float* __restrict__ b, int N) {
    int warp = (blockIdx.x * blockDim.x + threadIdx.x) >> 5;
    int lane = threadIdx.x & 31;
    if (warp >= N) return;

    const int beg = g_rowptr[warp];
    const int end = g_rowptr[warp + 1];

    float4 acc = make_float4(0.f, 0.f, 0.f, 0.f);
    int j = beg;
    int s = (j < end) ? g_srcs[j] : 0;
    for (; j < end; j++) {
        int snext = (j + 1 < end) ? g_srcs[j + 1] : 0;
        float4 v = *(const float4*)(g_y0 + (size_t)s * DHID + lane * 4);
        acc.x += v.x; acc.y += v.y; acc.z += v.z; acc.w += v.w;
        s = snext;
    }

    float inv = 1.0f / fmaxf((float)(end - beg), 1.0f);
    float4 z  = *(const float4*)(g_z0 + (size_t)warp * DHID + lane * 4);
    float4 bb = ((const float4*)b)[lane];
    float4 r;
    r.x = fmaxf(fmaf(acc.x, inv, bb.x + z.x), 0.f);
    r.y = fmaxf(fmaf(acc.y, inv, bb.y + z.y), 0.f);
    r.z = fmaxf(fmaf(acc.z, inv, bb.z + z.z), 0.f);
    r.w = fmaxf(fmaf(acc.w, inv, bb.w + z.w), 0.f);
    *(float4*)(g_h + (size_t)warp * DHID + lane * 4) = r;
}

// ---------------------------------------------------------------------------
// 8. layer-1 pull aggregation + fused finalize (half-warp/node -> d_out)
// ---------------------------------------------------------------------------
__global__ void agg1_kernel(const float* __restrict__ b,
                            float* __restrict__ out, int N) {
    int tid  = blockIdx.x * blockDim.x + threadIdx.x;
    int node = tid >> 4;
    int l    = tid & 15;
    if (node >= N) return;

    const int beg = g_rowptr[node];
    const int end = g_rowptr[node + 1];

    float4 acc = make_float4(0.f, 0.f, 0.f, 0.f);
    int j = beg;
    int s = (j < end) ? g_srcs[j] : 0;
    for (; j < end; j++) {
        int snext = (j + 1 < end) ? g_srcs[j + 1] : 0;
        float4 v = *(const float4*)(g_y1 + (size_t)s * DOUT + l * 4);
        acc.x += v.x; acc.y += v.y; acc.z += v.z; acc.w += v.w;
        s = snext;
    }

    float inv = 1.0f / fmaxf((float)(end - beg), 1.0f);
    float4 z  = *(const float4*)(g_z1 + (size_t)node * DOUT + l * 4);
    float4 bb = ((const float4*)b)[l];
    float4 r;
    r.x = fmaf(acc.x, inv, bb.x + z.x);
    r.y = fmaf(acc.y, inv, bb.y + z.y);
    r.z = fmaf(acc.z, inv, bb.z + z.z);
    r.w = fmaf(acc.w, inv, bb.w + z.w);
    *(float4*)(out + (size_t)node * DOUT + l * 4) = r;
}

// ---------------------------------------------------------------------------
extern "C" void kernel_launch(void* const* d_in, const int* in_sizes, int n_in,
                              void* d_out, int out_size) {
    const float* x    = (const float*)d_in[0];
    const void*  ei   = d_in[1];
    const float* W_l0 = (const float*)d_in[2];
    const float* b_l0 = (const float*)d_in[3];
    const float* W_r0 = (const float*)d_in[4];
    const float* W_l1 = (const float*)d_in[5];
    const float* b_l1 = (const float*)d_in[6];
    const float* W_r1 = (const float*)d_in[7];

    const int N = in_sizes[0] / DIN;
    const int E = in_sizes[1] / 2;
    const int NB = (N + SCAN_CHUNK - 1) / SCAN_CHUNK;

    // 0. edge dtype probe
    detect_kernel<<<1, 32>>>((const long long*)ei);

    // 1-4. CSR build (counting sort by dst)
    zc_kernel<<<(N + 256) / 256, 256>>>(N);
    hist_kernel<<<(E + 255) / 256, 256>>>(ei, E);
    breduce_kernel<<<NB, 256>>>(N);
    bscan_kernel<<<1, 256>>>(NB, N, E);
    lscan_kernel<<<NB, 256>>>(N);
    permute_kernel<<<(E + 255) / 256, 256>>>(ei, E);

    // 5. layer-0 dual GEMM
    gemm_dual_kernel<DHID, 0><<<(N + 63) / 64, 256>>>(x, W_l0, W_r0, N);

    // 6. layer-0 aggregation + finalize (warp/node)
    {
        long long threads = (long long)N * 32;
        agg0_kernel<<<(unsigned)((threads + 255) / 256), 256>>>(b_l0, N);
    }

    // 7. layer-1 dual GEMM
    gemm_dual_kernel<DOUT, 1><<<(N + 63) / 64, 256>>>(nullptr, W_l1, W_r1, N);

    // 8. layer-1 aggregation + finalize (half-warp/node)
    {
        long long threads = (long long)N * 16;
        agg1_kernel<<<(unsigned)((threads + 255) / 256), 256>>>(b_l1, (float*)d_out, N);
    }
}

// round 9
// speedup vs baseline: 1.5391x; 1.1761x over previous
#include <cuda_runtime.h>
#include <cuda_bf16.h>
#include <cstdint>

// ---------------------------------------------------------------------------
// GraphSAGE 2-layer, N=100000, E=1.6M, 128 -> 128 -> 64, fp32.
//
// R9: GEMMs moved from FFMA SIMT (~270us) to tensor pipe via
// mma.sync.m16n8k8 TF32 with 2-term operand split (Ah*Bh + Al*Bh + Ah*Bl),
// keeping fp32-class accuracy (~2e-7). hi/lo interleaved in smem so one
// LDS.64 fetches both terms of a fragment element.
//
// Pipeline (single stream, graph-capturable, allocation-free):
//   0. detect   : edge dtype probe (int64 vs int32)
//   1. zc       : zero per-node counters
//   2. hist     : counts[dst]++
//   3. breduce/bscan/lscan : multi-block exclusive scan -> rowptr, wroff
//   4. permute  : srcs[atomicAdd(wroff[dst])] = src   (counting sort)
//   5. gemm x2  : y0 = x @ W_l0 ; z0 = x @ W_r0        (tf32 split mma)
//   6. agg0     : warp/node: h = relu(mean_gather(y0) + b_l0 + z0)
//   7. gemm x2  : y1 = h @ W_l1 ; z1 = h @ W_r1
//   8. agg1     : half-warp/node: out = mean_gather(y1) + b_l1 + z1
// ---------------------------------------------------------------------------

#define MAXN 100000
#define MAXE 1600000
#define DIN  128
#define DHID 128
#define DOUT 64

#define SCAN_CHUNK 1024
#define MAXB ((MAXN + SCAN_CHUNK - 1) / SCAN_CHUNK + 1)

__device__ __align__(16) float g_y0[(size_t)MAXN * DHID];
__device__ __align__(16) float g_z0[(size_t)MAXN * DHID];
__device__ __align__(16) float g_h [(size_t)MAXN * DHID];
__device__ __align__(16) float g_y1[(size_t)MAXN * DOUT];
__device__ __align__(16) float g_z1[(size_t)MAXN * DOUT];
__device__ int g_rowptr[MAXN + 1];
__device__ int g_wroff [MAXN + 1];
__device__ int g_srcs  [MAXE];
__device__ int g_bsum  [MAXB];
__device__ int g_is64;

// ---------------------------------------------------------------------------
// 0. dtype probe
// ---------------------------------------------------------------------------
__global__ void detect_kernel(const long long* __restrict__ p) {
    if (threadIdx.x == 0 && blockIdx.x == 0) {
        int ok = 1;
        for (int i = 0; i < 64; i++) {
            long long v = p[i];
            if (v < 0 || v >= (1LL << 31)) { ok = 0; break; }
        }
        g_is64 = ok;
    }
}

__global__ void zc_kernel(int N) {
    int i = blockIdx.x * blockDim.x + threadIdx.x;
    if (i <= N) g_wroff[i] = 0;
}

__device__ __forceinline__ int edge_id(const void* ei, size_t idx) {
    return g_is64 ? (int)((const long long*)ei)[idx]
                  : ((const int*)ei)[idx];
}

__global__ void hist_kernel(const void* __restrict__ ei, int E) {
    int e = blockIdx.x * blockDim.x + threadIdx.x;
    if (e >= E) return;
    int d = edge_id(ei, (size_t)E + e);
    atomicAdd(&g_wroff[d], 1);
}

// ---------------------------------------------------------------------------
// 3a. per-chunk reduce
// ---------------------------------------------------------------------------
__global__ void __launch_bounds__(256)
breduce_kernel(int N) {
    __shared__ int sh[8];
    int t = threadIdx.x;
    int base = blockIdx.x * SCAN_CHUNK + t * 4;
    int s = 0;
#pragma unroll
    for (int i = 0; i < 4; i++) {
        int idx = base + i;
        if (idx < N) s += g_wroff[idx];
    }
#pragma unroll
    for (int off = 16; off > 0; off >>= 1)
        s += __shfl_down_sync(0xffffffffu, s, off);
    if ((t & 31) == 0) sh[t >> 5] = s;
    __syncthreads();
    if (t == 0) {
        int tot = 0;
#pragma unroll
        for (int i = 0; i < 8; i++) tot += sh[i];
        g_bsum[blockIdx.x] = tot;
    }
}

// ---------------------------------------------------------------------------
// 3b. scan chunk partials
// ---------------------------------------------------------------------------
__global__ void __launch_bounds__(256)
bscan_kernel(int nb, int N, int E) {
    __shared__ int sh[256];
    int t = threadIdx.x;
    int v = (t < nb) ? g_bsum[t] : 0;
    sh[t] = v;
    __syncthreads();
    for (int off = 1; off < 256; off <<= 1) {
        int u = (t >= off) ? sh[t - off] : 0;
        __syncthreads();
        sh[t] += u;
        __syncthreads();
    }
    if (t < nb) g_bsum[t] = sh[t] - v;
    if (t == 0) g_rowptr[N] = E;
}

// ---------------------------------------------------------------------------
// 3c. in-chunk exclusive scan + offset
// ---------------------------------------------------------------------------
__global__ void __launch_bounds__(256)
lscan_kernel(int N) {
    __shared__ int wsum[8];
    int t    = threadIdx.x;
    int lane = t & 31;
    int wid  = t >> 5;
    int base = blockIdx.x * SCAN_CHUNK + t * 4;

    int c[4];
#pragma unroll
    for (int i = 0; i < 4; i++) {
        int idx = base + i;
        c[i] = (idx < N) ? g_wroff[idx] : 0;
    }
    int tsum = c[0] + c[1] + c[2] + c[3];

    int incl = tsum;
#pragma unroll
    for (int off = 1; off < 32; off <<= 1) {
        int u = __shfl_up_sync(0xffffffffu, incl, off);
        if (lane >= off) incl += u;
    }
    if (lane == 31) wsum[wid] = incl;
    __syncthreads();
    if (wid == 0) {
        int w = (lane < 8) ? wsum[lane] : 0;
#pragma unroll
        for (int off = 1; off < 8; off <<= 1) {
            int u = __shfl_up_sync(0xffffffffu, w, off);
            if (lane >= off) w += u;
        }
        if (lane < 8) wsum[lane] = w;
    }
    __syncthreads();

    int run = incl - tsum
            + ((wid > 0) ? wsum[wid - 1] : 0)
            + g_bsum[blockIdx.x];
#pragma unroll
    for (int i = 0; i < 4; i++) {
        int idx = base + i;
        if (idx < N) { g_rowptr[idx] = run; g_wroff[idx] = run; run += c[i]; }
    }
}

// ---------------------------------------------------------------------------
// 4. counting-sort permute
// ---------------------------------------------------------------------------
__global__ void permute_kernel(const void* __restrict__ ei, int E) {
    int e = blockIdx.x * blockDim.x + threadIdx.x;
    if (e >= E) return;
    int s = edge_id(ei, (size_t)e);
    int d = edge_id(ei, (size_t)E + e);
    int pos = atomicAdd(&g_wroff[d], 1);
    g_srcs[pos] = s;
}

// ---------------------------------------------------------------------------
// TF32 helpers
// ---------------------------------------------------------------------------
__device__ __forceinline__ uint32_t f2tf32(float x) {
    uint32_t r;
    asm("cvt.rna.tf32.f32 %0, %1;" : "=r"(r) : "f"(x));
    return r;
}
__device__ __forceinline__ uint32_t fu(float x) { return __float_as_uint(x); }

__device__ __forceinline__ void mma_tf32(float* d, const uint32_t* a,
                                         const uint32_t* b) {
    asm volatile(
        "mma.sync.aligned.m16n8k8.row.col.f32.tf32.tf32.f32 "
        "{%0,%1,%2,%3}, {%4,%5,%6,%7}, {%8,%9}, {%0,%1,%2,%3};\n"
        : "+f"(d[0]), "+f"(d[1]), "+f"(d[2]), "+f"(d[3])
        : "r"(a[0]), "r"(a[1]), "r"(a[2]), "r"(a[3]),
          "r"(b[0]), "r"(b[1]));
}

// ---------------------------------------------------------------------------
// 5/7. TF32-split GEMM: Y = A @ W.  A:[N,128], W:[128,CO].
// WHICH: 0 -> y0 = x@Wl0, 1 -> z0 = x@Wr0, 2 -> y1 = h@Wl1, 3 -> z1 = h@Wr1.
// BM=128 rows/block, BK=16, 256 thr (8 warps), warp = 16 rows x CO cols.
// hi/lo split interleaved in smem (float2 per logical element).
// ---------------------------------------------------------------------------
template <int CO, int WHICH>
__global__ void __launch_bounds__(256)
gemm_tf32_kernel(const float* __restrict__ Aext,
                 const float* __restrict__ W, int N)
{
    constexpr int BM = 128, BK = 16, K = 128;
    constexpr int NT  = CO / 8;          // n-tiles per warp
    constexpr int AST = 2 * BM + 8;      // smem row stride (floats)
    constexpr int WST = 2 * CO + 8;

    const float* __restrict__ A = (WHICH < 2) ? Aext : (const float*)g_h;
    float* __restrict__ Y =
        (WHICH == 0) ? g_y0 : (WHICH == 1) ? g_z0 :
        (WHICH == 2) ? g_y1 : g_z1;

    __shared__ __align__(16) float As[BK][AST];
    __shared__ __align__(16) float Ws[BK][WST];

    const int tid  = threadIdx.x;
    const int lane = tid & 31;
    const int warp = tid >> 5;
    const int tg   = lane & 3;           // threadID_in_group
    const int grp  = lane >> 2;          // groupID
    const int row0 = blockIdx.x * BM;

    float acc[NT][4];
#pragma unroll
    for (int t = 0; t < NT; t++)
#pragma unroll
        for (int i = 0; i < 4; i++) acc[t][i] = 0.f;

    for (int k0 = 0; k0 < K; k0 += BK) {
        // ---- stage A chunk: BM x BK, split to (hi,lo) interleaved ----
#pragma unroll
        for (int i = tid; i < BM * BK / 4; i += 256) {
            int r  = i >> 2;                 // 0..127
            int kq = (i & 3) << 2;           // 0,4,8,12
            float4 v = (row0 + r < N)
                ? *(const float4*)(A + (size_t)(row0 + r) * K + k0 + kq)
                : make_float4(0.f, 0.f, 0.f, 0.f);
            float vv[4] = {v.x, v.y, v.z, v.w};
#pragma unroll
            for (int j = 0; j < 4; j++) {
                uint32_t hb = f2tf32(vv[j]);
                float    hf = __uint_as_float(hb);
                uint32_t lb = f2tf32(vv[j] - hf);
                *(float2*)&As[kq + j][2 * r] =
                    make_float2(hf, __uint_as_float(lb));
            }
        }
        // ---- stage W chunk: BK x CO, split interleaved ----
#pragma unroll
        for (int i = tid; i < BK * CO / 4; i += 256) {
            int kr = i / (CO / 4);
            int cq = (i % (CO / 4)) << 2;
            float4 v = *(const float4*)(W + (size_t)(k0 + kr) * CO + cq);
            float vv[4] = {v.x, v.y, v.z, v.w};
            float o[8];
#pragma unroll
            for (int j = 0; j < 4; j++) {
                uint32_t hb = f2tf32(vv[j]);
                float    hf = __uint_as_float(hb);
                uint32_t lb = f2tf32(vv[j] - hf);
                o[2 * j] = hf; o[2 * j + 1] = __uint_as_float(lb);
            }
            *(float4*)&Ws[kr][2 * cq]     = make_float4(o[0], o[1], o[2], o[3]);
            *(float4*)&Ws[kr][2 * cq + 4] = make_float4(o[4], o[5], o[6], o[7]);
        }
        __syncthreads();

        // ---- compute: 2 k8 steps per chunk ----
#pragma unroll
        for (int ks = 0; ks < BK / 8; ks++) {
            const int kb = ks * 8;
            float2 a0 = *(float2*)&As[kb + tg    ][2 * (warp * 16 + grp)];
            float2 a1 = *(float2*)&As[kb + tg    ][2 * (warp * 16 + grp + 8)];
            float2 a2 = *(float2*)&As[kb + tg + 4][2 * (warp * 16 + grp)];
            float2 a3 = *(float2*)&As[kb + tg + 4][2 * (warp * 16 + grp + 8)];
            uint32_t ah[4] = {fu(a0.x), fu(a1.x), fu(a2.x), fu(a3.x)};
            uint32_t al[4] = {fu(a0.y), fu(a1.y), fu(a2.y), fu(a3.y)};
#pragma unroll
            for (int t = 0; t < NT; t++) {
                float2 b0 = *(float2*)&Ws[kb + tg    ][2 * (t * 8 + grp)];
                float2 b1 = *(float2*)&Ws[kb + tg + 4][2 * (t * 8 + grp)];
                uint32_t bh[2] = {fu(b0.x), fu(b1.x)};
                uint32_t bl[2] = {fu(b0.y), fu(b1.y)};
                mma_tf32(acc[t], ah, bh);   // hi * hi
                mma_tf32(acc[t], al, bh);   // lo * hi
                mma_tf32(acc[t], ah, bl);   // hi * lo
            }
        }
        __syncthreads();
    }

    // ---- epilogue: c0,c1 at (row, 2tg), c2,c3 at (row+8, 2tg) ----
    const int r0 = row0 + warp * 16 + grp;
    const int r1 = r0 + 8;
#pragma unroll
    for (int t = 0; t < NT; t++) {
        int col = t * 8 + tg * 2;
        if (r0 < N)
            *(float2*)(Y + (size_t)r0 * CO + col) = make_float2(acc[t][0], acc[t][1]);
        if (r1 < N)
            *(float2*)(Y + (size_t)r1 * CO + col) = make_float2(acc[t][2], acc[t][3]);
    }
}

// ---------------------------------------------------------------------------
// 6. layer-0 pull aggregation + fused finalize (warp/node, no atomics)
// ---------------------------------------------------------------------------
__global__ void agg0_kernel(const float* __restrict__ b, int N) {
    int warp = (blockIdx.x * blockDim.x + threadIdx.x) >> 5;
    int lane = threadIdx.x & 31;
    if (warp >= N) return;

    const int beg = g_rowptr[warp];
    const int end = g_rowptr[warp + 1];

    float4 acc = make_float4(0.f, 0.f, 0.f, 0.f);
    int j = beg;
    int s = (j < end) ? g_srcs[j] : 0;
    for (; j < end; j++) {
        int snext = (j + 1 < end) ? g_srcs[j + 1] : 0;
        float4 v = *(const float4*)(g_y0 + (size_t)s * DHID + lane * 4);
        acc.x += v.x; acc.y += v.y; acc.z += v.z; acc.w += v.w;
        s = snext;
    }

    float inv = 1.0f / fmaxf((float)(end - beg), 1.0f);
    float4 z  = *(const float4*)(g_z0 + (size_t)warp * DHID + lane * 4);
    float4 bb = ((const float4*)b)[lane];
    float4 r;
    r.x = fmaxf(fmaf(acc.x, inv, bb.x + z.x), 0.f);
    r.y = fmaxf(fmaf(acc.y, inv, bb.y + z.y), 0.f);
    r.z = fmaxf(fmaf(acc.z, inv, bb.z + z.z), 0.f);
    r.w = fmaxf(fmaf(acc.w, inv, bb.w + z.w), 0.f);
    *(float4*)(g_h + (size_t)warp * DHID + lane * 4) = r;
}

// ---------------------------------------------------------------------------
// 8. layer-1 pull aggregation + fused finalize (half-warp/node -> d_out)
// ---------------------------------------------------------------------------
__global__ void agg1_kernel(const float* __restrict__ b,
                            float* __restrict__ out, int N) {
    int tid  = blockIdx.x * blockDim.x + threadIdx.x;
    int node = tid >> 4;
    int l    = tid & 15;
    if (node >= N) return;

    const int beg = g_rowptr[node];
    const int end = g_rowptr[node + 1];

    float4 acc = make_float4(0.f, 0.f, 0.f, 0.f);
    int j = beg;
    int s = (j < end) ? g_srcs[j] : 0;
    for (; j < end; j++) {
        int snext = (j + 1 < end) ? g_srcs[j + 1] : 0;
        float4 v = *(const float4*)(g_y1 + (size_t)s * DOUT + l * 4);
        acc.x += v.x; acc.y += v.y; acc.z += v.z; acc.w += v.w;
        s = snext;
    }

    float inv = 1.0f / fmaxf((float)(end - beg), 1.0f);
    float4 z  = *(const float4*)(g_z1 + (size_t)node * DOUT + l * 4);
    float4 bb = ((const float4*)b)[l];
    float4 r;
    r.x = fmaf(acc.x, inv, bb.x + z.x);
    r.y = fmaf(acc.y, inv, bb.y + z.y);
    r.z = fmaf(acc.z, inv, bb.z + z.z);
    r.w = fmaf(acc.w, inv, bb.w + z.w);
    *(float4*)(out + (size_t)node * DOUT + l * 4) = r;
}

// ---------------------------------------------------------------------------
extern "C" void kernel_launch(void* const* d_in, const int* in_sizes, int n_in,
                              void* d_out, int out_size) {
    const float* x    = (const float*)d_in[0];
    const void*  ei   = d_in[1];
    const float* W_l0 = (const float*)d_in[2];
    const float* b_l0 = (const float*)d_in[3];
    const float* W_r0 = (const float*)d_in[4];
    const float* W_l1 = (const float*)d_in[5];
    const float* b_l1 = (const float*)d_in[6];
    const float* W_r1 = (const float*)d_in[7];

    const int N  = in_sizes[0] / DIN;
    const int E  = in_sizes[1] / 2;
    const int NB = (N + SCAN_CHUNK - 1) / SCAN_CHUNK;
    const int GB = (N + 127) / 128;     // gemm blocks

    // 0. edge dtype probe
    detect_kernel<<<1, 32>>>((const long long*)ei);

    // 1-4. CSR build (counting sort by dst)
    zc_kernel<<<(N + 256) / 256, 256>>>(N);
    hist_kernel<<<(E + 255) / 256, 256>>>(ei, E);
    breduce_kernel<<<NB, 256>>>(N);
    bscan_kernel<<<1, 256>>>(NB, N, E);
    lscan_kernel<<<NB, 256>>>(N);
    permute_kernel<<<(E + 255) / 256, 256>>>(ei, E);

    // 5. layer-0 GEMMs (tf32 split mma)
    gemm_tf32_kernel<DHID, 0><<<GB, 256>>>(x, W_l0, N);
    gemm_tf32_kernel<DHID, 1><<<GB, 256>>>(x, W_r0, N);

    // 6. layer-0 aggregation + finalize (warp/node)
    {
        long long threads = (long long)N * 32;
        agg0_kernel<<<(unsigned)((threads + 255) / 256), 256>>>(b_l0, N);
    }

    // 7. layer-1 GEMMs
    gemm_tf32_kernel<DOUT, 2><<<GB, 256>>>(nullptr, W_l1, N);
    gemm_tf32_kernel<DOUT, 3><<<GB, 256>>>(nullptr, W_r1, N);

    // 8. layer-1 aggregation + finalize (half-warp/node)
    {
        long long threads = (long long)N * 16;
        agg1_kernel<<<(unsigned)((threads + 255) / 256), 256>>>(b_l1, (float*)d_out, N);
    }
}

// round 15
// speedup vs baseline: 1.9911x; 1.2937x over previous
#include <cuda_runtime.h>
#include <cuda_bf16.h>
#include <cstdint>

// ---------------------------------------------------------------------------
// GraphSAGE 2-layer, N=100000, E=1.6M, 128 -> 128 -> 64, fp32.
//
// R11 = R10 with the fatal bug fixed: R10 passed __device__ globals
// (g_y0/g_z0) as kernel args FROM HOST code -> garbage pointer -> faulting
// stores -> dead context -> poisoned output (rel_err exactly 1.0).
// Outputs are now selected inside the kernel via the template parameter.
//
//  - 2-term TF32 split (Ah*B + Al*B, B plain tf32): mma count -33%,
//    W staging halved. Accuracy = fp32-A x tf32-B ~ 2e-4 aggregate.
//  - CSR build hidden inside GEMM kernels: hist blocks prepended to the
//    y0-GEMM grid, permute blocks prepended to the z0-GEMM grid.
//  - layer-1 GEMMs fused into one dual kernel sharing staged/split A.
//  - agg kernels unrolled x2 (two gather loads in flight).
//
// Launches:
//   1. detect+zc   : dtype probe + zero counters
//   2. G0a         : hist (HB blocks) + y0 = x @ W_l0
//   3. breduce  4. bscan  5. lscan      (multi-block exclusive scan)
//   6. G0b         : permute (PB blocks) + z0 = x @ W_r0
//   7. agg0        : h = relu(mean_gather(y0) + b_l0 + z0)
//   8. G1          : y1 = h @ W_l1 ; z1 = h @ W_r1  (dual, shared A)
//   9. agg1        : out = mean_gather(y1) + b_l1 + z1
// ---------------------------------------------------------------------------

#define MAXN 100000
#define MAXE 1600000
#define DIN  128
#define DHID 128
#define DOUT 64

#define SCAN_CHUNK 1024
#define MAXB ((MAXN + SCAN_CHUNK - 1) / SCAN_CHUNK + 1)

#define HB 512     // hist blocks prepended to G0a
#define PB 512     // permute blocks prepended to G0b

__device__ __align__(16) float g_y0[(size_t)MAXN * DHID];
__device__ __align__(16) float g_z0[(size_t)MAXN * DHID];
__device__ __align__(16) float g_h [(size_t)MAXN * DHID];
__device__ __align__(16) float g_y1[(size_t)MAXN * DOUT];
__device__ __align__(16) float g_z1[(size_t)MAXN * DOUT];
__device__ int g_rowptr[MAXN + 1];
__device__ int g_wroff [MAXN + 1];
__device__ int g_srcs  [MAXE];
__device__ int g_bsum  [MAXB];
__device__ int g_is64;

// ---------------------------------------------------------------------------
// 1. fused dtype probe + counter zeroing
// ---------------------------------------------------------------------------
__global__ void detect_zc_kernel(const long long* __restrict__ p, int N) {
    int i = blockIdx.x * blockDim.x + threadIdx.x;
    if (i <= N) g_wroff[i] = 0;
    if (i == 0) {
        int ok = 1;
        for (int k = 0; k < 64; k++) {
            long long v = p[k];
            if (v < 0 || v >= (1LL << 31)) { ok = 0; break; }
        }
        g_is64 = ok;
    }
}

// ---------------------------------------------------------------------------
// scan kernels (unchanged, known-good since R8)
// ---------------------------------------------------------------------------
__global__ void __launch_bounds__(256)
breduce_kernel(int N) {
    __shared__ int sh[8];
    int t = threadIdx.x;
    int base = blockIdx.x * SCAN_CHUNK + t * 4;
    int s = 0;
#pragma unroll
    for (int i = 0; i < 4; i++) {
        int idx = base + i;
        if (idx < N) s += g_wroff[idx];
    }
#pragma unroll
    for (int off = 16; off > 0; off >>= 1)
        s += __shfl_down_sync(0xffffffffu, s, off);
    if ((t & 31) == 0) sh[t >> 5] = s;
    __syncthreads();
    if (t == 0) {
        int tot = 0;
#pragma unroll
        for (int i = 0; i < 8; i++) tot += sh[i];
        g_bsum[blockIdx.x] = tot;
    }
}

__global__ void __launch_bounds__(256)
bscan_kernel(int nb, int N, int E) {
    __shared__ int sh[256];
    int t = threadIdx.x;
    int v = (t < nb) ? g_bsum[t] : 0;
    sh[t] = v;
    __syncthreads();
    for (int off = 1; off < 256; off <<= 1) {
        int u = (t >= off) ? sh[t - off] : 0;
        __syncthreads();
        sh[t] += u;
        __syncthreads();
    }
    if (t < nb) g_bsum[t] = sh[t] - v;
    if (t == 0) g_rowptr[N] = E;
}

__global__ void __launch_bounds__(256)
lscan_kernel(int N) {
    __shared__ int wsum[8];
    int t    = threadIdx.x;
    int lane = t & 31;
    int wid  = t >> 5;
    int base = blockIdx.x * SCAN_CHUNK + t * 4;

    int c[4];
#pragma unroll
    for (int i = 0; i < 4; i++) {
        int idx = base + i;
        c[i] = (idx < N) ? g_wroff[idx] : 0;
    }
    int tsum = c[0] + c[1] + c[2] + c[3];

    int incl = tsum;
#pragma unroll
    for (int off = 1; off < 32; off <<= 1) {
        int u = __shfl_up_sync(0xffffffffu, incl, off);
        if (lane >= off) incl += u;
    }
    if (lane == 31) wsum[wid] = incl;
    __syncthreads();
    if (wid == 0) {
        int w = (lane < 8) ? wsum[lane] : 0;
#pragma unroll
        for (int off = 1; off < 8; off <<= 1) {
            int u = __shfl_up_sync(0xffffffffu, w, off);
            if (lane >= off) w += u;
        }
        if (lane < 8) wsum[lane] = w;
    }
    __syncthreads();

    int run = incl - tsum
            + ((wid > 0) ? wsum[wid - 1] : 0)
            + g_bsum[blockIdx.x];
#pragma unroll
    for (int i = 0; i < 4; i++) {
        int idx = base + i;
        if (idx < N) { g_rowptr[idx] = run; g_wroff[idx] = run; run += c[i]; }
    }
}

// ---------------------------------------------------------------------------
// TF32 helpers
// ---------------------------------------------------------------------------
__device__ __forceinline__ uint32_t f2tf32(float x) {
    uint32_t r;
    asm("cvt.rna.tf32.f32 %0, %1;" : "=r"(r) : "f"(x));
    return r;
}
__device__ __forceinline__ uint32_t fu(float x) { return __float_as_uint(x); }

__device__ __forceinline__ void mma_tf32(float* d, const uint32_t* a,
                                         const uint32_t* b) {
    asm volatile(
        "mma.sync.aligned.m16n8k8.row.col.f32.tf32.tf32.f32 "
        "{%0,%1,%2,%3}, {%4,%5,%6,%7}, {%8,%9}, {%0,%1,%2,%3};\n"
        : "+f"(d[0]), "+f"(d[1]), "+f"(d[2]), "+f"(d[3])
        : "r"(a[0]), "r"(a[1]), "r"(a[2]), "r"(a[3]),
          "r"(b[0]), "r"(b[1]));
}

// ---------------------------------------------------------------------------
// G0a / G0b: single-W TF32 GEMM (BM=128, A hi/lo split, W plain tf32)
// EXTRA=0: HB hist blocks prepended, writes Y = g_y0 (selected DEVICE-side).
// EXTRA=1: PB permute blocks prepended, writes Y = g_z0.
// ---------------------------------------------------------------------------
__device__ __forceinline__ int edge_id_dyn(const void* ei, size_t idx) {
    return g_is64 ? (int)((const long long*)ei)[idx]
                  : ((const int*)ei)[idx];
}

template <int EXTRA>
__global__ void __launch_bounds__(256)
gemm0_kernel(const float* __restrict__ A,
             const float* __restrict__ W,
             const void* __restrict__ ei,
             int N, int E)
{
    constexpr int XB = (EXTRA == 0) ? HB : PB;
    // device-side global selection (the R10 bug was passing these from host)
    float* __restrict__ Y = (EXTRA == 0) ? g_y0 : g_z0;

    // ---- prepended irregular work ----
    if (blockIdx.x < XB) {
        int t0     = blockIdx.x * 256 + threadIdx.x;
        int stride = XB * 256;
        if (EXTRA == 0) {            // hist: counts[dst]++
            for (int e = t0; e < E; e += stride) {
                int d = edge_id_dyn(ei, (size_t)E + e);
                atomicAdd(&g_wroff[d], 1);
            }
        } else {                     // permute: counting-sort srcs by dst
            for (int e = t0; e < E; e += stride) {
                int s = edge_id_dyn(ei, (size_t)e);
                int d = edge_id_dyn(ei, (size_t)E + e);
                int pos = atomicAdd(&g_wroff[d], 1);
                g_srcs[pos] = s;
            }
        }
        return;
    }

    // ---- GEMM ----
    constexpr int BM = 128, BK = 16, K = 128, CO = 128;
    constexpr int NT  = CO / 8;
    constexpr int AST = 2 * BM + 8;
    constexpr int WST = CO + 8;

    __shared__ __align__(16) float As[BK][AST];
    __shared__ __align__(16) float Ws[BK][WST];

    const int tid  = threadIdx.x;
    const int lane = tid & 31;
    const int warp = tid >> 5;
    const int tg   = lane & 3;
    const int grp  = lane >> 2;
    const int row0 = ((int)blockIdx.x - XB) * BM;

    float acc[NT][4];
#pragma unroll
    for (int t = 0; t < NT; t++)
#pragma unroll
        for (int i = 0; i < 4; i++) acc[t][i] = 0.f;

    for (int k0 = 0; k0 < K; k0 += BK) {
        // stage A chunk (hi/lo interleaved)
#pragma unroll
        for (int i = tid; i < BM * BK / 4; i += 256) {
            int r  = i >> 2;
            int kq = (i & 3) << 2;
            float4 v = (row0 + r < N)
                ? *(const float4*)(A + (size_t)(row0 + r) * K + k0 + kq)
                : make_float4(0.f, 0.f, 0.f, 0.f);
            float vv[4] = {v.x, v.y, v.z, v.w};
#pragma unroll
            for (int j = 0; j < 4; j++) {
                uint32_t hb = f2tf32(vv[j]);
                float    hf = __uint_as_float(hb);
                uint32_t lb = f2tf32(vv[j] - hf);
                *(float2*)&As[kq + j][2 * r] =
                    make_float2(hf, __uint_as_float(lb));
            }
        }
        // stage W chunk (plain tf32)
#pragma unroll
        for (int i = tid; i < BK * CO / 4; i += 256) {
            int kr = i / (CO / 4);
            int cq = (i % (CO / 4)) << 2;
            float4 v = *(const float4*)(W + (size_t)(k0 + kr) * CO + cq);
            float4 o;
            o.x = __uint_as_float(f2tf32(v.x));
            o.y = __uint_as_float(f2tf32(v.y));
            o.z = __uint_as_float(f2tf32(v.z));
            o.w = __uint_as_float(f2tf32(v.w));
            *(float4*)&Ws[kr][cq] = o;
        }
        __syncthreads();

#pragma unroll
        for (int ks = 0; ks < BK / 8; ks++) {
            const int kb = ks * 8;
            float2 a0 = *(float2*)&As[kb + tg    ][2 * (warp * 16 + grp)];
            float2 a1 = *(float2*)&As[kb + tg    ][2 * (warp * 16 + grp + 8)];
            float2 a2 = *(float2*)&As[kb + tg + 4][2 * (warp * 16 + grp)];
            float2 a3 = *(float2*)&As[kb + tg + 4][2 * (warp * 16 + grp + 8)];
            uint32_t ah[4] = {fu(a0.x), fu(a1.x), fu(a2.x), fu(a3.x)};
            uint32_t al[4] = {fu(a0.y), fu(a1.y), fu(a2.y), fu(a3.y)};
#pragma unroll
            for (int t = 0; t < NT; t++) {
                uint32_t b[2] = {fu(Ws[kb + tg    ][t * 8 + grp]),
                                 fu(Ws[kb + tg + 4][t * 8 + grp])};
                mma_tf32(acc[t], ah, b);
                mma_tf32(acc[t], al, b);
            }
        }
        __syncthreads();
    }

    const int r0 = row0 + warp * 16 + grp;
    const int r1 = r0 + 8;
#pragma unroll
    for (int t = 0; t < NT; t++) {
        int col = t * 8 + tg * 2;
        if (r0 < N)
            *(float2*)(Y + (size_t)r0 * CO + col) = make_float2(acc[t][0], acc[t][1]);
        if (r1 < N)
            *(float2*)(Y + (size_t)r1 * CO + col) = make_float2(acc[t][2], acc[t][3]);
    }
}

// ---------------------------------------------------------------------------
// G1: dual TF32 GEMM, shared split A: y1 = h @ W_l1, z1 = h @ W_r1 (CO=64)
// (all globals referenced device-side only)
// ---------------------------------------------------------------------------
__global__ void __launch_bounds__(256)
gemm1_dual_kernel(const float* __restrict__ Wl,
                  const float* __restrict__ Wr, int N)
{
    constexpr int BM = 128, BK = 16, K = 128, CO = 64;
    constexpr int NT  = CO / 8;          // 8
    constexpr int AST = 2 * BM + 8;
    constexpr int WST = CO + 8;

    const float* __restrict__ A = g_h;

    __shared__ __align__(16) float As [BK][AST];
    __shared__ __align__(16) float Wsl[BK][WST];
    __shared__ __align__(16) float Wsr[BK][WST];

    const int tid  = threadIdx.x;
    const int lane = tid & 31;
    const int warp = tid >> 5;
    const int tg   = lane & 3;
    const int grp  = lane >> 2;
    const int row0 = blockIdx.x * BM;

    float accl[NT][4], accr[NT][4];
#pragma unroll
    for (int t = 0; t < NT; t++)
#pragma unroll
        for (int i = 0; i < 4; i++) { accl[t][i] = 0.f; accr[t][i] = 0.f; }

    for (int k0 = 0; k0 < K; k0 += BK) {
#pragma unroll
        for (int i = tid; i < BM * BK / 4; i += 256) {
            int r  = i >> 2;
            int kq = (i & 3) << 2;
            float4 v = (row0 + r < N)
                ? *(const float4*)(A + (size_t)(row0 + r) * K + k0 + kq)
                : make_float4(0.f, 0.f, 0.f, 0.f);
            float vv[4] = {v.x, v.y, v.z, v.w};
#pragma unroll
            for (int j = 0; j < 4; j++) {
                uint32_t hb = f2tf32(vv[j]);
                float    hf = __uint_as_float(hb);
                uint32_t lb = f2tf32(vv[j] - hf);
                *(float2*)&As[kq + j][2 * r] =
                    make_float2(hf, __uint_as_float(lb));
            }
        }
        // both W chunks, plain tf32 (16*64/4 = 256 float4 each, 1/thread)
        {
            int i  = tid;
            int kr = i / (CO / 4);
            int cq = (i % (CO / 4)) << 2;
            float4 v = *(const float4*)(Wl + (size_t)(k0 + kr) * CO + cq);
            float4 o;
            o.x = __uint_as_float(f2tf32(v.x));
            o.y = __uint_as_float(f2tf32(v.y));
            o.z = __uint_as_float(f2tf32(v.z));
            o.w = __uint_as_float(f2tf32(v.w));
            *(float4*)&Wsl[kr][cq] = o;
            float4 u = *(const float4*)(Wr + (size_t)(k0 + kr) * CO + cq);
            float4 p;
            p.x = __uint_as_float(f2tf32(u.x));
            p.y = __uint_as_float(f2tf32(u.y));
            p.z = __uint_as_float(f2tf32(u.z));
            p.w = __uint_as_float(f2tf32(u.w));
            *(float4*)&Wsr[kr][cq] = p;
        }
        __syncthreads();

#pragma unroll
        for (int ks = 0; ks < BK / 8; ks++) {
            const int kb = ks * 8;
            float2 a0 = *(float2*)&As[kb + tg    ][2 * (warp * 16 + grp)];
            float2 a1 = *(float2*)&As[kb + tg    ][2 * (warp * 16 + grp + 8)];
            float2 a2 = *(float2*)&As[kb + tg + 4][2 * (warp * 16 + grp)];
            float2 a3 = *(float2*)&As[kb + tg + 4][2 * (warp * 16 + grp + 8)];
            uint32_t ah[4] = {fu(a0.x), fu(a1.x), fu(a2.x), fu(a3.x)};
            uint32_t al[4] = {fu(a0.y), fu(a1.y), fu(a2.y), fu(a3.y)};
#pragma unroll
            for (int t = 0; t < NT; t++) {
                uint32_t bl[2] = {fu(Wsl[kb + tg    ][t * 8 + grp]),
                                  fu(Wsl[kb + tg + 4][t * 8 + grp])};
                uint32_t br[2] = {fu(Wsr[kb + tg    ][t * 8 + grp]),
                                  fu(Wsr[kb + tg + 4][t * 8 + grp])};
                mma_tf32(accl[t], ah, bl);
                mma_tf32(accl[t], al, bl);
                mma_tf32(accr[t], ah, br);
                mma_tf32(accr[t], al, br);
            }
        }
        __syncthreads();
    }

    const int r0 = row0 + warp * 16 + grp;
    const int r1 = r0 + 8;
#pragma unroll
    for (int t = 0; t < NT; t++) {
        int col = t * 8 + tg * 2;
        if (r0 < N) {
            *(float2*)(g_y1 + (size_t)r0 * CO + col) = make_float2(accl[t][0], accl[t][1]);
            *(float2*)(g_z1 + (size_t)r0 * CO + col) = make_float2(accr[t][0], accr[t][1]);
        }
        if (r1 < N) {
            *(float2*)(g_y1 + (size_t)r1 * CO + col) = make_float2(accl[t][2], accl[t][3]);
            *(float2*)(g_z1 + (size_t)r1 * CO + col) = make_float2(accr[t][2], accr[t][3]);
        }
    }
}

// ---------------------------------------------------------------------------
// agg0: warp/node pull aggregation + fused finalize, unroll x2
// ---------------------------------------------------------------------------
__global__ void agg0_kernel(const float* __restrict__ b, int N) {
    int warp = (blockIdx.x * blockDim.x + threadIdx.x) >> 5;
    int lane = threadIdx.x & 31;
    if (warp >= N) return;

    const int beg = g_rowptr[warp];
    const int end = g_rowptr[warp + 1];

    float4 acc0 = make_float4(0.f, 0.f, 0.f, 0.f);
    float4 acc1 = make_float4(0.f, 0.f, 0.f, 0.f);
    int j = beg;
    for (; j + 2 <= end; j += 2) {
        int s0 = g_srcs[j];
        int s1 = g_srcs[j + 1];
        float4 v0 = *(const float4*)(g_y0 + (size_t)s0 * DHID + lane * 4);
        float4 v1 = *(const float4*)(g_y0 + (size_t)s1 * DHID + lane * 4);
        acc0.x += v0.x; acc0.y += v0.y; acc0.z += v0.z; acc0.w += v0.w;
        acc1.x += v1.x; acc1.y += v1.y; acc1.z += v1.z; acc1.w += v1.w;
    }
    if (j < end) {
        int s0 = g_srcs[j];
        float4 v0 = *(const float4*)(g_y0 + (size_t)s0 * DHID + lane * 4);
        acc0.x += v0.x; acc0.y += v0.y; acc0.z += v0.z; acc0.w += v0.w;
    }
    acc0.x += acc1.x; acc0.y += acc1.y; acc0.z += acc1.z; acc0.w += acc1.w;

    float inv = 1.0f / fmaxf((float)(end - beg), 1.0f);
    float4 z  = *(const float4*)(g_z0 + (size_t)warp * DHID + lane * 4);
    float4 bb = ((const float4*)b)[lane];
    float4 r;
    r.x = fmaxf(fmaf(acc0.x, inv, bb.x + z.x), 0.f);
    r.y = fmaxf(fmaf(acc0.y, inv, bb.y + z.y), 0.f);
    r.z = fmaxf(fmaf(acc0.z, inv, bb.z + z.z), 0.f);
    r.w = fmaxf(fmaf(acc0.w, inv, bb.w + z.w), 0.f);
    *(float4*)(g_h + (size_t)warp * DHID + lane * 4) = r;
}

// ---------------------------------------------------------------------------
// agg1: half-warp/node pull aggregation + fused finalize, unroll x2
// ---------------------------------------------------------------------------
__global__ void agg1_kernel(const float* __restrict__ b,
                            float* __restrict__ out, int N) {
    int tid  = blockIdx.x * blockDim.x + threadIdx.x;
    int node = tid >> 4;
    int l    = tid & 15;
    if (node >= N) return;

    const int beg = g_rowptr[node];
    const int end = g_rowptr[node + 1];

    float4 acc0 = make_float4(0.f, 0.f, 0.f, 0.f);
    float4 acc1 = make_float4(0.f, 0.f, 0.f, 0.f);
    int j = beg;
    for (; j + 2 <= end; j += 2) {
        int s0 = g_srcs[j];
        int s1 = g_srcs[j + 1];
        float4 v0 = *(const float4*)(g_y1 + (size_t)s0 * DOUT + l * 4);
        float4 v1 = *(const float4*)(g_y1 + (size_t)s1 * DOUT + l * 4);
        acc0.x += v0.x; acc0.y += v0.y; acc0.z += v0.z; acc0.w += v0.w;
        acc1.x += v1.x; acc1.y += v1.y; acc1.z += v1.z; acc1.w += v1.w;
    }
    if (j < end) {
        int s0 = g_srcs[j];
        float4 v0 = *(const float4*)(g_y1 + (size_t)s0 * DOUT + l * 4);
        acc0.x += v0.x; acc0.y += v0.y; acc0.z += v0.z; acc0.w += v0.w;
    }
    acc0.x += acc1.x; acc0.y += acc1.y; acc0.z += acc1.z; acc0.w += acc1.w;

    float inv = 1.0f / fmaxf((float)(end - beg), 1.0f);
    float4 z  = *(const float4*)(g_z1 + (size_t)node * DOUT + l * 4);
    float4 bb = ((const float4*)b)[l];
    float4 r;
    r.x = fmaf(acc0.x, inv, bb.x + z.x);
    r.y = fmaf(acc0.y, inv, bb.y + z.y);
    r.z = fmaf(acc0.z, inv, bb.z + z.z);
    r.w = fmaf(acc0.w, inv, bb.w + z.w);
    *(float4*)(out + (size_t)node * DOUT + l * 4) = r;
}

// ---------------------------------------------------------------------------
extern "C" void kernel_launch(void* const* d_in, const int* in_sizes, int n_in,
                              void* d_out, int out_size) {
    const float* x    = (const float*)d_in[0];
    const void*  ei   = d_in[1];
    const float* W_l0 = (const float*)d_in[2];
    const float* b_l0 = (const float*)d_in[3];
    const float* W_r0 = (const float*)d_in[4];
    const float* W_l1 = (const float*)d_in[5];
    const float* b_l1 = (const float*)d_in[6];
    const float* W_r1 = (const float*)d_in[7];

    const int N  = in_sizes[0] / DIN;
    const int E  = in_sizes[1] / 2;
    const int NB = (N + SCAN_CHUNK - 1) / SCAN_CHUNK;
    const int GB = (N + 127) / 128;

    // 1. probe + zero counters
    detect_zc_kernel<<<(N + 256) / 256, 256>>>((const long long*)ei, N);

    // 2. hist + y0 GEMM   (note: only harness pointers passed as args)
    gemm0_kernel<0><<<HB + GB, 256>>>(x, W_l0, ei, N, E);

    // 3-5. exclusive scan -> rowptr, wroff
    breduce_kernel<<<NB, 256>>>(N);
    bscan_kernel<<<1, 256>>>(NB, N, E);
    lscan_kernel<<<NB, 256>>>(N);

    // 6. permute + z0 GEMM
    gemm0_kernel<1><<<PB + GB, 256>>>(x, W_r0, ei, N, E);

    // 7. layer-0 aggregation + finalize
    {
        long long threads = (long long)N * 32;
        agg0_kernel<<<(unsigned)((threads + 255) / 256), 256>>>(b_l0, N);
    }

    // 8. layer-1 dual GEMM (shared A)
    gemm1_dual_kernel<<<GB, 256>>>(W_l1, W_r1, N);

    // 9. layer-1 aggregation + finalize
    {
        long long threads = (long long)N * 16;
        agg1_kernel<<<(unsigned)((threads + 255) / 256), 256>>>(b_l1, (float*)d_out, N);
    }
}

// round 16
// speedup vs baseline: 2.0131x; 1.0110x over previous
#include <cuda_runtime.h>
#include <cuda_bf16.h>
#include <cuda_fp16.h>
#include <cstdint>

// ---------------------------------------------------------------------------
// GraphSAGE 2-layer, N=100000, E=1.6M, 128 -> 128 -> 64, fp32.
//
// R16 = R11 + fp16 gather staging:
//   y0 / y1 are ONLY consumed via edge gathers, so the GEMM epilogues write
//   them directly as fp16 (no fp32 copy). Gather traffic halves
//   (819->410 MB layer 0, 410->205 MB layer 1); accumulation stays fp32;
//   z/bias terms stay fp32. Added error ~7e-5 abs (negligible vs tf32 2.9e-4).
//
// Launches:
//   1. detect+zc   : dtype probe + zero counters
//   2. G0a         : hist (HB blocks) + y0h = fp16(x @ W_l0)
//   3. breduce  4. bscan  5. lscan      (multi-block exclusive scan)
//   6. G0b         : permute (PB blocks) + z0 = x @ W_r0
//   7. agg0        : h = relu(mean_gather(y0h) + b_l0 + z0)
//   8. G1          : y1h = fp16(h @ W_l1) ; z1 = h @ W_r1
//   9. agg1        : out = mean_gather(y1h) + b_l1 + z1
// ---------------------------------------------------------------------------

#define MAXN 100000
#define MAXE 1600000
#define DIN  128
#define DHID 128
#define DOUT 64

#define SCAN_CHUNK 1024
#define MAXB ((MAXN + SCAN_CHUNK - 1) / SCAN_CHUNK + 1)

#define HB 512     // hist blocks prepended to G0a
#define PB 512     // permute blocks prepended to G0b

__device__ __align__(16) __half g_y0h[(size_t)MAXN * DHID];
__device__ __align__(16) float  g_z0 [(size_t)MAXN * DHID];
__device__ __align__(16) float  g_h  [(size_t)MAXN * DHID];
__device__ __align__(16) __half g_y1h[(size_t)MAXN * DOUT];
__device__ __align__(16) float  g_z1 [(size_t)MAXN * DOUT];
__device__ int g_rowptr[MAXN + 1];
__device__ int g_wroff [MAXN + 1];
__device__ int g_srcs  [MAXE];
__device__ int g_bsum  [MAXB];
__device__ int g_is64;

// ---------------------------------------------------------------------------
// 1. fused dtype probe + counter zeroing
// ---------------------------------------------------------------------------
__global__ void detect_zc_kernel(const long long* __restrict__ p, int N) {
    int i = blockIdx.x * blockDim.x + threadIdx.x;
    if (i <= N) g_wroff[i] = 0;
    if (i == 0) {
        int ok = 1;
        for (int k = 0; k < 64; k++) {
            long long v = p[k];
            if (v < 0 || v >= (1LL << 31)) { ok = 0; break; }
        }
        g_is64 = ok;
    }
}

// ---------------------------------------------------------------------------
// scan kernels (known-good since R8)
// ---------------------------------------------------------------------------
__global__ void __launch_bounds__(256)
breduce_kernel(int N) {
    __shared__ int sh[8];
    int t = threadIdx.x;
    int base = blockIdx.x * SCAN_CHUNK + t * 4;
    int s = 0;
#pragma unroll
    for (int i = 0; i < 4; i++) {
        int idx = base + i;
        if (idx < N) s += g_wroff[idx];
    }
#pragma unroll
    for (int off = 16; off > 0; off >>= 1)
        s += __shfl_down_sync(0xffffffffu, s, off);
    if ((t & 31) == 0) sh[t >> 5] = s;
    __syncthreads();
    if (t == 0) {
        int tot = 0;
#pragma unroll
        for (int i = 0; i < 8; i++) tot += sh[i];
        g_bsum[blockIdx.x] = tot;
    }
}

__global__ void __launch_bounds__(256)
bscan_kernel(int nb, int N, int E) {
    __shared__ int sh[256];
    int t = threadIdx.x;
    int v = (t < nb) ? g_bsum[t] : 0;
    sh[t] = v;
    __syncthreads();
    for (int off = 1; off < 256; off <<= 1) {
        int u = (t >= off) ? sh[t - off] : 0;
        __syncthreads();
        sh[t] += u;
        __syncthreads();
    }
    if (t < nb) g_bsum[t] = sh[t] - v;
    if (t == 0) g_rowptr[N] = E;
}

__global__ void __launch_bounds__(256)
lscan_kernel(int N) {
    __shared__ int wsum[8];
    int t    = threadIdx.x;
    int lane = t & 31;
    int wid  = t >> 5;
    int base = blockIdx.x * SCAN_CHUNK + t * 4;

    int c[4];
#pragma unroll
    for (int i = 0; i < 4; i++) {
        int idx = base + i;
        c[i] = (idx < N) ? g_wroff[idx] : 0;
    }
    int tsum = c[0] + c[1] + c[2] + c[3];

    int incl = tsum;
#pragma unroll
    for (int off = 1; off < 32; off <<= 1) {
        int u = __shfl_up_sync(0xffffffffu, incl, off);
        if (lane >= off) incl += u;
    }
    if (lane == 31) wsum[wid] = incl;
    __syncthreads();
    if (wid == 0) {
        int w = (lane < 8) ? wsum[lane] : 0;
#pragma unroll
        for (int off = 1; off < 8; off <<= 1) {
            int u = __shfl_up_sync(0xffffffffu, w, off);
            if (lane >= off) w += u;
        }
        if (lane < 8) wsum[lane] = w;
    }
    __syncthreads();

    int run = incl - tsum
            + ((wid > 0) ? wsum[wid - 1] : 0)
            + g_bsum[blockIdx.x];
#pragma unroll
    for (int i = 0; i < 4; i++) {
        int idx = base + i;
        if (idx < N) { g_rowptr[idx] = run; g_wroff[idx] = run; run += c[i]; }
    }
}

// ---------------------------------------------------------------------------
// TF32 helpers
// ---------------------------------------------------------------------------
__device__ __forceinline__ uint32_t f2tf32(float x) {
    uint32_t r;
    asm("cvt.rna.tf32.f32 %0, %1;" : "=r"(r) : "f"(x));
    return r;
}
__device__ __forceinline__ uint32_t fu(float x) { return __float_as_uint(x); }

__device__ __forceinline__ void mma_tf32(float* d, const uint32_t* a,
                                         const uint32_t* b) {
    asm volatile(
        "mma.sync.aligned.m16n8k8.row.col.f32.tf32.tf32.f32 "
        "{%0,%1,%2,%3}, {%4,%5,%6,%7}, {%8,%9}, {%0,%1,%2,%3};\n"
        : "+f"(d[0]), "+f"(d[1]), "+f"(d[2]), "+f"(d[3])
        : "r"(a[0]), "r"(a[1]), "r"(a[2]), "r"(a[3]),
          "r"(b[0]), "r"(b[1]));
}

// ---------------------------------------------------------------------------
// G0a / G0b: single-W TF32 GEMM (BM=128, A hi/lo split, W plain tf32)
// EXTRA=0: HB hist blocks prepended, epilogue -> g_y0h (fp16).
// EXTRA=1: PB permute blocks prepended, epilogue -> g_z0 (fp32).
// ---------------------------------------------------------------------------
__device__ __forceinline__ int edge_id_dyn(const void* ei, size_t idx) {
    return g_is64 ? (int)((const long long*)ei)[idx]
                  : ((const int*)ei)[idx];
}

template <int EXTRA>
__global__ void __launch_bounds__(256)
gemm0_kernel(const float* __restrict__ A,
             const float* __restrict__ W,
             const void* __restrict__ ei,
             int N, int E)
{
    constexpr int XB = (EXTRA == 0) ? HB : PB;

    // ---- prepended irregular work ----
    if (blockIdx.x < XB) {
        int t0     = blockIdx.x * 256 + threadIdx.x;
        int stride = XB * 256;
        if (EXTRA == 0) {            // hist: counts[dst]++
            for (int e = t0; e < E; e += stride) {
                int d = edge_id_dyn(ei, (size_t)E + e);
                atomicAdd(&g_wroff[d], 1);
            }
        } else {                     // permute: counting-sort srcs by dst
            for (int e = t0; e < E; e += stride) {
                int s = edge_id_dyn(ei, (size_t)e);
                int d = edge_id_dyn(ei, (size_t)E + e);
                int pos = atomicAdd(&g_wroff[d], 1);
                g_srcs[pos] = s;
            }
        }
        return;
    }

    // ---- GEMM ----
    constexpr int BM = 128, BK = 16, K = 128, CO = 128;
    constexpr int NT  = CO / 8;
    constexpr int AST = 2 * BM + 8;
    constexpr int WST = CO + 8;

    __shared__ __align__(16) float As[BK][AST];
    __shared__ __align__(16) float Ws[BK][WST];

    const int tid  = threadIdx.x;
    const int lane = tid & 31;
    const int warp = tid >> 5;
    const int tg   = lane & 3;
    const int grp  = lane >> 2;
    const int row0 = ((int)blockIdx.x - XB) * BM;

    float acc[NT][4];
#pragma unroll
    for (int t = 0; t < NT; t++)
#pragma unroll
        for (int i = 0; i < 4; i++) acc[t][i] = 0.f;

    for (int k0 = 0; k0 < K; k0 += BK) {
        // stage A chunk (hi/lo interleaved)
#pragma unroll
        for (int i = tid; i < BM * BK / 4; i += 256) {
            int r  = i >> 2;
            int kq = (i & 3) << 2;
            float4 v = (row0 + r < N)
                ? *(const float4*)(A + (size_t)(row0 + r) * K + k0 + kq)
                : make_float4(0.f, 0.f, 0.f, 0.f);
            float vv[4] = {v.x, v.y, v.z, v.w};
#pragma unroll
            for (int j = 0; j < 4; j++) {
                uint32_t hb = f2tf32(vv[j]);
                float    hf = __uint_as_float(hb);
                uint32_t lb = f2tf32(vv[j] - hf);
                *(float2*)&As[kq + j][2 * r] =
                    make_float2(hf, __uint_as_float(lb));
            }
        }
        // stage W chunk (plain tf32)
#pragma unroll
        for (int i = tid; i < BK * CO / 4; i += 256) {
            int kr = i / (CO / 4);
            int cq = (i % (CO / 4)) << 2;
            float4 v = *(const float4*)(W + (size_t)(k0 + kr) * CO + cq);
            float4 o;
            o.x = __uint_as_float(f2tf32(v.x));
            o.y = __uint_as_float(f2tf32(v.y));
            o.z = __uint_as_float(f2tf32(v.z));
            o.w = __uint_as_float(f2tf32(v.w));
            *(float4*)&Ws[kr][cq] = o;
        }
        __syncthreads();

#pragma unroll
        for (int ks = 0; ks < BK / 8; ks++) {
            const int kb = ks * 8;
            float2 a0 = *(float2*)&As[kb + tg    ][2 * (warp * 16 + grp)];
            float2 a1 = *(float2*)&As[kb + tg    ][2 * (warp * 16 + grp + 8)];
            float2 a2 = *(float2*)&As[kb + tg + 4][2 * (warp * 16 + grp)];
            float2 a3 = *(float2*)&As[kb + tg + 4][2 * (warp * 16 + grp + 8)];
            uint32_t ah[4] = {fu(a0.x), fu(a1.x), fu(a2.x), fu(a3.x)};
            uint32_t al[4] = {fu(a0.y), fu(a1.y), fu(a2.y), fu(a3.y)};
#pragma unroll
            for (int t = 0; t < NT; t++) {
                uint32_t b[2] = {fu(Ws[kb + tg    ][t * 8 + grp]),
                                 fu(Ws[kb + tg + 4][t * 8 + grp])};
                mma_tf32(acc[t], ah, b);
                mma_tf32(acc[t], al, b);
            }
        }
        __syncthreads();
    }

    const int r0 = row0 + warp * 16 + grp;
    const int r1 = r0 + 8;
#pragma unroll
    for (int t = 0; t < NT; t++) {
        int col = t * 8 + tg * 2;
        if (EXTRA == 0) {   // y0 as fp16 (only consumed by the edge gather)
            if (r0 < N)
                *(__half2*)(g_y0h + (size_t)r0 * CO + col) =
                    __floats2half2_rn(acc[t][0], acc[t][1]);
            if (r1 < N)
                *(__half2*)(g_y0h + (size_t)r1 * CO + col) =
                    __floats2half2_rn(acc[t][2], acc[t][3]);
        } else {            // z0 stays fp32
            if (r0 < N)
                *(float2*)(g_z0 + (size_t)r0 * CO + col) =
                    make_float2(acc[t][0], acc[t][1]);
            if (r1 < N)
                *(float2*)(g_z0 + (size_t)r1 * CO + col) =
                    make_float2(acc[t][2], acc[t][3]);
        }
    }
}

// ---------------------------------------------------------------------------
// G1: dual TF32 GEMM, shared split A: y1h = fp16(h @ W_l1), z1 = h @ W_r1
// ---------------------------------------------------------------------------
__global__ void __launch_bounds__(256)
gemm1_dual_kernel(const float* __restrict__ Wl,
                  const float* __restrict__ Wr, int N)
{
    constexpr int BM = 128, BK = 16, K = 128, CO = 64;
    constexpr int NT  = CO / 8;          // 8
    constexpr int AST = 2 * BM + 8;
    constexpr int WST = CO + 8;

    const float* __restrict__ A = g_h;

    __shared__ __align__(16) float As [BK][AST];
    __shared__ __align__(16) float Wsl[BK][WST];
    __shared__ __align__(16) float Wsr[BK][WST];

    const int tid  = threadIdx.x;
    const int lane = tid & 31;
    const int warp = tid >> 5;
    const int tg   = lane & 3;
    const int grp  = lane >> 2;
    const int row0 = blockIdx.x * BM;

    float accl[NT][4], accr[NT][4];
#pragma unroll
    for (int t = 0; t < NT; t++)
#pragma unroll
        for (int i = 0; i < 4; i++) { accl[t][i] = 0.f; accr[t][i] = 0.f; }

    for (int k0 = 0; k0 < K; k0 += BK) {
#pragma unroll
        for (int i = tid; i < BM * BK / 4; i += 256) {
            int r  = i >> 2;
            int kq = (i & 3) << 2;
            float4 v = (row0 + r < N)
                ? *(const float4*)(A + (size_t)(row0 + r) * K + k0 + kq)
                : make_float4(0.f, 0.f, 0.f, 0.f);
            float vv[4] = {v.x, v.y, v.z, v.w};
#pragma unroll
            for (int j = 0; j < 4; j++) {
                uint32_t hb = f2tf32(vv[j]);
                float    hf = __uint_as_float(hb);
                uint32_t lb = f2tf32(vv[j] - hf);
                *(float2*)&As[kq + j][2 * r] =
                    make_float2(hf, __uint_as_float(lb));
            }
        }
        // both W chunks, plain tf32 (16*64/4 = 256 float4 each, 1/thread)
        {
            int i  = tid;
            int kr = i / (CO / 4);
            int cq = (i % (CO / 4)) << 2;
            float4 v = *(const float4*)(Wl + (size_t)(k0 + kr) * CO + cq);
            float4 o;
            o.x = __uint_as_float(f2tf32(v.x));
            o.y = __uint_as_float(f2tf32(v.y));
            o.z = __uint_as_float(f2tf32(v.z));
            o.w = __uint_as_float(f2tf32(v.w));
            *(float4*)&Wsl[kr][cq] = o;
            float4 u = *(const float4*)(Wr + (size_t)(k0 + kr) * CO + cq);
            float4 p;
            p.x = __uint_as_float(f2tf32(u.x));
            p.y = __uint_as_float(f2tf32(u.y));
            p.z = __uint_as_float(f2tf32(u.z));
            p.w = __uint_as_float(f2tf32(u.w));
            *(float4*)&Wsr[kr][cq] = p;
        }
        __syncthreads();

#pragma unroll
        for (int ks = 0; ks < BK / 8; ks++) {
            const int kb = ks * 8;
            float2 a0 = *(float2*)&As[kb + tg    ][2 * (warp * 16 + grp)];
            float2 a1 = *(float2*)&As[kb + tg    ][2 * (warp * 16 + grp + 8)];
            float2 a2 = *(float2*)&As[kb + tg + 4][2 * (warp * 16 + grp)];
            float2 a3 = *(float2*)&As[kb + tg + 4][2 * (warp * 16 + grp + 8)];
            uint32_t ah[4] = {fu(a0.x), fu(a1.x), fu(a2.x), fu(a3.x)};
            uint32_t al[4] = {fu(a0.y), fu(a1.y), fu(a2.y), fu(a3.y)};
#pragma unroll
            for (int t = 0; t < NT; t++) {
                uint32_t bl[2] = {fu(Wsl[kb + tg    ][t * 8 + grp]),
                                  fu(Wsl[kb + tg + 4][t * 8 + grp])};
                uint32_t br[2] = {fu(Wsr[kb + tg    ][t * 8 + grp]),
                                  fu(Wsr[kb + tg + 4][t * 8 + grp])};
                mma_tf32(accl[t], ah, bl);
                mma_tf32(accl[t], al, bl);
                mma_tf32(accr[t], ah, br);
                mma_tf32(accr[t], al, br);
            }
        }
        __syncthreads();
    }

    const int r0 = row0 + warp * 16 + grp;
    const int r1 = r0 + 8;
#pragma unroll
    for (int t = 0; t < NT; t++) {
        int col = t * 8 + tg * 2;
        if (r0 < N) {
            *(__half2*)(g_y1h + (size_t)r0 * CO + col) =
                __floats2half2_rn(accl[t][0], accl[t][1]);
            *(float2*)(g_z1 + (size_t)r0 * CO + col) =
                make_float2(accr[t][0], accr[t][1]);
        }
        if (r1 < N) {
            *(__half2*)(g_y1h + (size_t)r1 * CO + col) =
                __floats2half2_rn(accl[t][2], accl[t][3]);
            *(float2*)(g_z1 + (size_t)r1 * CO + col) =
                make_float2(accr[t][2], accr[t][3]);
        }
    }
}

// ---------------------------------------------------------------------------
// fp16 row fragment -> float4 accumulate helper
// ---------------------------------------------------------------------------
__device__ __forceinline__ void acc_half4(float4& acc, uint2 u) {
    float2 f01 = __half22float2(*(__half2*)&u.x);
    float2 f23 = __half22float2(*(__half2*)&u.y);
    acc.x += f01.x; acc.y += f01.y; acc.z += f23.x; acc.w += f23.y;
}

// ---------------------------------------------------------------------------
// agg0: warp/node pull aggregation (fp16 gather) + fused finalize, unroll x2
// ---------------------------------------------------------------------------
__global__ void agg0_kernel(const float* __restrict__ b, int N) {
    int warp = (blockIdx.x * blockDim.x + threadIdx.x) >> 5;
    int lane = threadIdx.x & 31;
    if (warp >= N) return;

    const int beg = g_rowptr[warp];
    const int end = g_rowptr[warp + 1];

    float4 acc0 = make_float4(0.f, 0.f, 0.f, 0.f);
    float4 acc1 = make_float4(0.f, 0.f, 0.f, 0.f);
    int j = beg;
    for (; j + 2 <= end; j += 2) {
        int s0 = g_srcs[j];
        int s1 = g_srcs[j + 1];
        uint2 u0 = *((const uint2*)(g_y0h + (size_t)s0 * DHID) + lane);
        uint2 u1 = *((const uint2*)(g_y0h + (size_t)s1 * DHID) + lane);
        acc_half4(acc0, u0);
        acc_half4(acc1, u1);
    }
    if (j < end) {
        int s0 = g_srcs[j];
        uint2 u0 = *((const uint2*)(g_y0h + (size_t)s0 * DHID) + lane);
        acc_half4(acc0, u0);
    }
    acc0.x += acc1.x; acc0.y += acc1.y; acc0.z += acc1.z; acc0.w += acc1.w;

    float inv = 1.0f / fmaxf((float)(end - beg), 1.0f);
    float4 z  = *(const float4*)(g_z0 + (size_t)warp * DHID + lane * 4);
    float4 bb = ((const float4*)b)[lane];
    float4 r;
    r.x = fmaxf(fmaf(acc0.x, inv, bb.x + z.x), 0.f);
    r.y = fmaxf(fmaf(acc0.y, inv, bb.y + z.y), 0.f);
    r.z = fmaxf(fmaf(acc0.z, inv, bb.z + z.z), 0.f);
    r.w = fmaxf(fmaf(acc0.w, inv, bb.w + z.w), 0.f);
    *(float4*)(g_h + (size_t)warp * DHID + lane * 4) = r;
}

// ---------------------------------------------------------------------------
// agg1: half-warp/node pull aggregation (fp16 gather) + finalize, unroll x2
// ---------------------------------------------------------------------------
__global__ void agg1_kernel(const float* __restrict__ b,
                            float* __restrict__ out, int N) {
    int tid  = blockIdx.x * blockDim.x + threadIdx.x;
    int node = tid >> 4;
    int l    = tid & 15;
    if (node >= N) return;

    const int beg = g_rowptr[node];
    const int end = g_rowptr[node + 1];

    float4 acc0 = make_float4(0.f, 0.f, 0.f, 0.f);
    float4 acc1 = make_float4(0.f, 0.f, 0.f, 0.f);
    int j = beg;
    for (; j + 2 <= end; j += 2) {
        int s0 = g_srcs[j];
        int s1 = g_srcs[j + 1];
        uint2 u0 = *((const uint2*)(g_y1h + (size_t)s0 * DOUT) + l);
        uint2 u1 = *((const uint2*)(g_y1h + (size_t)s1 * DOUT) + l);
        acc_half4(acc0, u0);
        acc_half4(acc1, u1);
    }
    if (j < end) {
        int s0 = g_srcs[j];
        uint2 u0 = *((const uint2*)(g_y1h + (size_t)s0 * DOUT) + l);
        acc_half4(acc0, u0);
    }
    acc0.x += acc1.x; acc0.y += acc1.y; acc0.z += acc1.z; acc0.w += acc1.w;

    float inv = 1.0f / fmaxf((float)(end - beg), 1.0f);
    float4 z  = *(const float4*)(g_z1 + (size_t)node * DOUT + l * 4);
    float4 bb = ((const float4*)b)[l];
    float4 r;
    r.x = fmaf(acc0.x, inv, bb.x + z.x);
    r.y = fmaf(acc0.y, inv, bb.y + z.y);
    r.z = fmaf(acc0.z, inv, bb.z + z.z);
    r.w = fmaf(acc0.w, inv, bb.w + z.w);
    *(float4*)(out + (size_t)node * DOUT + l * 4) = r;
}

// ---------------------------------------------------------------------------
extern "C" void kernel_launch(void* const* d_in, const int* in_sizes, int n_in,
                              void* d_out, int out_size) {
    const float* x    = (const float*)d_in[0];
    const void*  ei   = d_in[1];
    const float* W_l0 = (const float*)d_in[2];
    const float* b_l0 = (const float*)d_in[3];
    const float* W_r0 = (const float*)d_in[4];
    const float* W_l1 = (const float*)d_in[5];
    const float* b_l1 = (const float*)d_in[6];
    const float* W_r1 = (const float*)d_in[7];

    const int N  = in_sizes[0] / DIN;
    const int E  = in_sizes[1] / 2;
    const int NB = (N + SCAN_CHUNK - 1) / SCAN_CHUNK;
    const int GB = (N + 127) / 128;

    // 1. probe + zero counters
    detect_zc_kernel<<<(N + 256) / 256, 256>>>((const long long*)ei, N);

    // 2. hist + y0h GEMM
    gemm0_kernel<0><<<HB + GB, 256>>>(x, W_l0, ei, N, E);

    // 3-5. exclusive scan -> rowptr, wroff
    breduce_kernel<<<NB, 256>>>(N);
    bscan_kernel<<<1, 256>>>(NB, N, E);
    lscan_kernel<<<NB, 256>>>(N);

    // 6. permute + z0 GEMM
    gemm0_kernel<1><<<PB + GB, 256>>>(x, W_r0, ei, N, E);

    // 7. layer-0 aggregation + finalize
    {
        long long threads = (long long)N * 32;
        agg0_kernel<<<(unsigned)((threads + 255) / 256), 256>>>(b_l0, N);
    }

    // 8. layer-1 dual GEMM (shared A)
    gemm1_dual_kernel<<<GB, 256>>>(W_l1, W_r1, N);

    // 9. layer-1 aggregation + finalize
    {
        long long threads = (long long)N * 16;
        agg1_kernel<<<(unsigned)((threads + 255) / 256), 256>>>(b_l1, (float*)d_out, N);
    }
}